// round 1
// baseline (speedup 1.0000x reference)
#include <cuda_runtime.h>

#define BATCH   2
#define SEQ     2048
#define DMODEL  1024
#define HEADS   16
#define DHEAD   64
#define MTOT    (BATCH * SEQ)   // 4096

// Scratch (allocation-free rule: __device__ globals)
__device__ float g_Q[MTOT * DMODEL];
__device__ float g_K[MTOT * DMODEL];
__device__ float g_V[MTOT * DMODEL];
__device__ float g_C[MTOT * DMODEL];

// ---------------------------------------------------------------------------
// SGEMM:  C[M,N] = A[M,K] @ W[N,K]^T + bias[N]
// M=4096, N=1024, K=1024.  128x128 block tile, BK=8, 256 threads, 8x8 micro.
// ---------------------------------------------------------------------------
__global__ __launch_bounds__(256) void sgemm_nt_bias(
    const float* __restrict__ A, const float* __restrict__ W,
    const float* __restrict__ bias, float* __restrict__ C)
{
    const int K = DMODEL;
    const int N = DMODEL;

    __shared__ float As[8][128];
    __shared__ float Bs[8][128];

    const int tid = threadIdx.x;
    const int tx = tid & 15;     // 0..15  -> col group
    const int ty = tid >> 4;     // 0..15  -> row group

    const int block_m = blockIdx.y * 128;
    const int block_n = blockIdx.x * 128;

    const int lrow = tid >> 1;          // 0..127
    const int lk4  = (tid & 1) * 4;     // 0 or 4

    const float* Aptr = A + (size_t)(block_m + lrow) * K + lk4;
    const float* Wptr = W + (size_t)(block_n + lrow) * K + lk4;

    float acc[8][8];
    #pragma unroll
    for (int i = 0; i < 8; i++)
        #pragma unroll
        for (int j = 0; j < 8; j++) acc[i][j] = 0.f;

    for (int kt = 0; kt < K; kt += 8) {
        float4 a4 = *(const float4*)(Aptr + kt);
        float4 w4 = *(const float4*)(Wptr + kt);
        As[lk4 + 0][lrow] = a4.x;
        As[lk4 + 1][lrow] = a4.y;
        As[lk4 + 2][lrow] = a4.z;
        As[lk4 + 3][lrow] = a4.w;
        Bs[lk4 + 0][lrow] = w4.x;
        Bs[lk4 + 1][lrow] = w4.y;
        Bs[lk4 + 2][lrow] = w4.z;
        Bs[lk4 + 3][lrow] = w4.w;
        __syncthreads();

        #pragma unroll
        for (int k = 0; k < 8; k++) {
            float a[8], b[8];
            float4 t0 = *(const float4*)&As[k][ty * 8 + 0];
            float4 t1 = *(const float4*)&As[k][ty * 8 + 4];
            a[0]=t0.x; a[1]=t0.y; a[2]=t0.z; a[3]=t0.w;
            a[4]=t1.x; a[5]=t1.y; a[6]=t1.z; a[7]=t1.w;
            float4 u0 = *(const float4*)&Bs[k][tx * 8 + 0];
            float4 u1 = *(const float4*)&Bs[k][tx * 8 + 4];
            b[0]=u0.x; b[1]=u0.y; b[2]=u0.z; b[3]=u0.w;
            b[4]=u1.x; b[5]=u1.y; b[6]=u1.z; b[7]=u1.w;
            #pragma unroll
            for (int i = 0; i < 8; i++)
                #pragma unroll
                for (int j = 0; j < 8; j++)
                    acc[i][j] += a[i] * b[j];
        }
        __syncthreads();
    }

    // Epilogue with bias
    const int col0 = block_n + tx * 8;
    float4 bia0 = *(const float4*)(bias + col0);
    float4 bia1 = *(const float4*)(bias + col0 + 4);
    #pragma unroll
    for (int i = 0; i < 8; i++) {
        const int row = block_m + ty * 8 + i;
        float4 o0, o1;
        o0.x = acc[i][0] + bia0.x; o0.y = acc[i][1] + bia0.y;
        o0.z = acc[i][2] + bia0.z; o0.w = acc[i][3] + bia0.w;
        o1.x = acc[i][4] + bia1.x; o1.y = acc[i][5] + bia1.y;
        o1.z = acc[i][6] + bia1.z; o1.w = acc[i][7] + bia1.w;
        *(float4*)(C + (size_t)row * N + col0)     = o0;
        *(float4*)(C + (size_t)row * N + col0 + 4) = o1;
    }
}

// ---------------------------------------------------------------------------
// Flash attention (fp32): one thread = one query row.
// Block = 128 threads = 128 queries of one (b,h). K/V tiled 64 keys in smem.
// Online softmax in chunks of 16 keys (chunk loop rolled to bound code size).
// ---------------------------------------------------------------------------
#define AT_BK 64
#define AT_CH 16

__global__ __launch_bounds__(128) void attn_kernel(
    const float* __restrict__ Qp, const float* __restrict__ Kp,
    const float* __restrict__ Vp, float* __restrict__ Ctx)
{
    __shared__ float Ks[AT_BK][68];   // padded rows: 68*4=272B, 16B aligned
    __shared__ float Vs[AT_BK][68];

    const int tid  = threadIdx.x;
    const int b    = blockIdx.z;
    const int h    = blockIdx.y;
    const int qrow = blockIdx.x * 128 + tid;
    const float scale = 0.125f;   // 1/sqrt(64)

    float q[64], o[64];
    const float* qp = Qp + ((size_t)(b * SEQ + qrow)) * DMODEL + h * DHEAD;
    #pragma unroll
    for (int d4 = 0; d4 < 16; d4++) {
        float4 v = *(const float4*)(qp + d4 * 4);
        q[d4*4+0] = v.x * scale; q[d4*4+1] = v.y * scale;
        q[d4*4+2] = v.z * scale; q[d4*4+3] = v.w * scale;
    }
    #pragma unroll
    for (int d = 0; d < 64; d++) o[d] = 0.f;

    float m = -1e30f, l = 0.f;

    const float* kbase = Kp + ((size_t)b * SEQ) * DMODEL + h * DHEAD;
    const float* vbase = Vp + ((size_t)b * SEQ) * DMODEL + h * DHEAD;

    for (int kt = 0; kt < SEQ; kt += AT_BK) {
        // Cooperative tile load: 64 keys * 16 float4, 8 float4 per thread
        #pragma unroll
        for (int r = 0; r < 8; r++) {
            int li  = r * 128 + tid;
            int key = li >> 4;
            int d4  = li & 15;
            *(float4*)&Ks[key][d4 * 4] =
                *(const float4*)(kbase + (size_t)(kt + key) * DMODEL + d4 * 4);
            *(float4*)&Vs[key][d4 * 4] =
                *(const float4*)(vbase + (size_t)(kt + key) * DMODEL + d4 * 4);
        }
        __syncthreads();

        for (int c = 0; c < AT_BK / AT_CH; c++) {   // rolled
            float s[AT_CH];
            #pragma unroll
            for (int j = 0; j < AT_CH; j++) s[j] = 0.f;

            #pragma unroll
            for (int d4 = 0; d4 < 16; d4++) {
                #pragma unroll
                for (int j = 0; j < AT_CH; j++) {
                    float4 k4 = *(const float4*)&Ks[c * AT_CH + j][d4 * 4];
                    s[j] += q[d4*4+0]*k4.x + q[d4*4+1]*k4.y
                          + q[d4*4+2]*k4.z + q[d4*4+3]*k4.w;
                }
            }

            float mloc = s[0];
            #pragma unroll
            for (int j = 1; j < AT_CH; j++) mloc = fmaxf(mloc, s[j]);
            float mnew = fmaxf(m, mloc);
            float corr = __expf(m - mnew);
            float psum = 0.f;
            #pragma unroll
            for (int j = 0; j < AT_CH; j++) { s[j] = __expf(s[j] - mnew); psum += s[j]; }
            l = l * corr + psum;
            m = mnew;
            #pragma unroll
            for (int d = 0; d < 64; d++) o[d] *= corr;

            #pragma unroll
            for (int j = 0; j < AT_CH; j++) {
                float p = s[j];
                #pragma unroll
                for (int d4 = 0; d4 < 16; d4++) {
                    float4 v4 = *(const float4*)&Vs[c * AT_CH + j][d4 * 4];
                    o[d4*4+0] += p * v4.x; o[d4*4+1] += p * v4.y;
                    o[d4*4+2] += p * v4.z; o[d4*4+3] += p * v4.w;
                }
            }
        }
        __syncthreads();
    }

    const float inv = 1.f / l;
    float* cp = Ctx + ((size_t)(b * SEQ + qrow)) * DMODEL + h * DHEAD;
    #pragma unroll
    for (int d4 = 0; d4 < 16; d4++) {
        float4 v;
        v.x = o[d4*4+0] * inv; v.y = o[d4*4+1] * inv;
        v.z = o[d4*4+2] * inv; v.w = o[d4*4+3] * inv;
        *(float4*)(cp + d4 * 4) = v;
    }
}

// ---------------------------------------------------------------------------
extern "C" void kernel_launch(void* const* d_in, const int* in_sizes, int n_in,
                              void* d_out, int out_size)
{
    const float* x  = (const float*)d_in[0];
    const float* Wq = (const float*)d_in[1];
    const float* bq = (const float*)d_in[2];
    const float* Wk = (const float*)d_in[3];
    const float* bk = (const float*)d_in[4];
    const float* Wv = (const float*)d_in[5];
    const float* bv = (const float*)d_in[6];
    const float* Wo = (const float*)d_in[7];
    const float* bo = (const float*)d_in[8];
    float* out = (float*)d_out;

    float *Qd, *Kd, *Vd, *Cd;
    cudaGetSymbolAddress((void**)&Qd, g_Q);
    cudaGetSymbolAddress((void**)&Kd, g_K);
    cudaGetSymbolAddress((void**)&Vd, g_V);
    cudaGetSymbolAddress((void**)&Cd, g_C);

    dim3 ggrid(DMODEL / 128, MTOT / 128);   // (8, 32)
    sgemm_nt_bias<<<ggrid, 256>>>(x, Wq, bq, Qd);
    sgemm_nt_bias<<<ggrid, 256>>>(x, Wk, bk, Kd);
    sgemm_nt_bias<<<ggrid, 256>>>(x, Wv, bv, Vd);

    dim3 agrid(SEQ / 128, HEADS, BATCH);    // (16, 16, 2)
    attn_kernel<<<agrid, 128>>>(Qd, Kd, Vd, Cd);

    sgemm_nt_bias<<<ggrid, 256>>>(Cd, Wo, bo, out);
}

// round 2
// speedup vs baseline: 2.0105x; 2.0105x over previous
#include <cuda_runtime.h>
#include <cstdint>

#define BATCH   2
#define SEQ     2048
#define DMODEL  1024
#define HEADS   16
#define DHEAD   64
#define MTOT    (BATCH * SEQ)   // 4096

// Scratch (allocation-free rule: __device__ globals)
__device__ float g_Q[MTOT * DMODEL];
__device__ float g_K[MTOT * DMODEL];
__device__ float g_V[MTOT * DMODEL];
__device__ float g_C[MTOT * DMODEL];

// ---------------------------------------------------------------------------
// helpers
// ---------------------------------------------------------------------------
__device__ __forceinline__ float tf32r(float x) {
    uint32_t u;
    asm("cvt.rna.tf32.f32 %0, %1;" : "=r"(u) : "f"(x));
    return __uint_as_float(u);
}
__device__ __forceinline__ uint32_t fu(float x) { return __float_as_uint(x); }

// D += A * B  (m16n8k8, tf32, fp32 accum)
__device__ __forceinline__ void mma8(float* d, const uint32_t* a, const uint32_t* b) {
    asm volatile(
        "mma.sync.aligned.m16n8k8.row.col.f32.tf32.tf32.f32 "
        "{%0,%1,%2,%3}, {%4,%5,%6,%7}, {%8,%9}, {%0,%1,%2,%3};\n"
        : "+f"(d[0]), "+f"(d[1]), "+f"(d[2]), "+f"(d[3])
        : "r"(a[0]), "r"(a[1]), "r"(a[2]), "r"(a[3]), "r"(b[0]), "r"(b[1]));
}

// ---------------------------------------------------------------------------
// TF32 GEMM:  C[M,N] = A[M,K] @ W[N,K]^T + bias[N]
// M=4096, N=1024, K=1024.  Block 128x128, BK=16, 256 thr (8 warps 4Mx2N),
// warp tile 32x64, double-buffered smem.
// ---------------------------------------------------------------------------
__global__ __launch_bounds__(256) void gemm_tf32(
    const float* __restrict__ A, const float* __restrict__ W,
    const float* __restrict__ bias, float* __restrict__ C)
{
    __shared__ float As[2][16][132];
    __shared__ float Bs[2][16][132];

    const int tid  = threadIdx.x;
    const int lane = tid & 31;
    const int warp = tid >> 5;
    const int gid  = lane >> 2;
    const int tig  = lane & 3;
    const int m0   = (warp >> 1) * 32;   // warp M origin in tile
    const int n0w  = (warp & 1) * 64;    // warp N origin in tile

    const int block_m = blockIdx.y * 128;
    const int block_n = blockIdx.x * 128;

    const int lrow = tid >> 1;           // 0..127
    const int lk0  = (tid & 1) * 8;      // 0 or 8: this thread's 8-float k span

    const float* Aptr = A + (size_t)(block_m + lrow) * DMODEL + lk0;
    const float* Wptr = W + (size_t)(block_n + lrow) * DMODEL + lk0;

    float acc[2][8][4];
    #pragma unroll
    for (int mt = 0; mt < 2; mt++)
        #pragma unroll
        for (int nt = 0; nt < 8; nt++)
            #pragma unroll
            for (int r = 0; r < 4; r++) acc[mt][nt][r] = 0.f;

    // prologue: stage tile 0 into buffer 0
    {
        float4 a0 = *(const float4*)(Aptr);
        float4 a1 = *(const float4*)(Aptr + 4);
        float4 b0 = *(const float4*)(Wptr);
        float4 b1 = *(const float4*)(Wptr + 4);
        As[0][lk0+0][lrow]=tf32r(a0.x); As[0][lk0+1][lrow]=tf32r(a0.y);
        As[0][lk0+2][lrow]=tf32r(a0.z); As[0][lk0+3][lrow]=tf32r(a0.w);
        As[0][lk0+4][lrow]=tf32r(a1.x); As[0][lk0+5][lrow]=tf32r(a1.y);
        As[0][lk0+6][lrow]=tf32r(a1.z); As[0][lk0+7][lrow]=tf32r(a1.w);
        Bs[0][lk0+0][lrow]=tf32r(b0.x); Bs[0][lk0+1][lrow]=tf32r(b0.y);
        Bs[0][lk0+2][lrow]=tf32r(b0.z); Bs[0][lk0+3][lrow]=tf32r(b0.w);
        Bs[0][lk0+4][lrow]=tf32r(b1.x); Bs[0][lk0+5][lrow]=tf32r(b1.y);
        Bs[0][lk0+6][lrow]=tf32r(b1.z); Bs[0][lk0+7][lrow]=tf32r(b1.w);
    }
    __syncthreads();

    const int NK = DMODEL / 16;   // 64
    for (int kt = 0; kt < NK; ++kt) {
        const int cur = kt & 1;
        float4 pa0, pa1, pb0, pb1;
        if (kt < NK - 1) {
            const float* ap = Aptr + (kt + 1) * 16;
            const float* wp = Wptr + (kt + 1) * 16;
            pa0 = *(const float4*)(ap);
            pa1 = *(const float4*)(ap + 4);
            pb0 = *(const float4*)(wp);
            pb1 = *(const float4*)(wp + 4);
        }

        #pragma unroll
        for (int ks = 0; ks < 2; ++ks) {
            uint32_t af[2][4], bf[8][2];
            #pragma unroll
            for (int mt = 0; mt < 2; mt++) {
                const int mr = m0 + mt * 16 + gid;
                af[mt][0] = fu(As[cur][ks*8 + tig    ][mr    ]);
                af[mt][1] = fu(As[cur][ks*8 + tig    ][mr + 8]);
                af[mt][2] = fu(As[cur][ks*8 + tig + 4][mr    ]);
                af[mt][3] = fu(As[cur][ks*8 + tig + 4][mr + 8]);
            }
            #pragma unroll
            for (int nt = 0; nt < 8; nt++) {
                const int nc = n0w + nt * 8 + gid;
                bf[nt][0] = fu(Bs[cur][ks*8 + tig    ][nc]);
                bf[nt][1] = fu(Bs[cur][ks*8 + tig + 4][nc]);
            }
            #pragma unroll
            for (int mt = 0; mt < 2; mt++)
                #pragma unroll
                for (int nt = 0; nt < 8; nt++)
                    mma8(acc[mt][nt], af[mt], bf[nt]);
        }

        if (kt < NK - 1) {
            const int nxt = cur ^ 1;
            As[nxt][lk0+0][lrow]=tf32r(pa0.x); As[nxt][lk0+1][lrow]=tf32r(pa0.y);
            As[nxt][lk0+2][lrow]=tf32r(pa0.z); As[nxt][lk0+3][lrow]=tf32r(pa0.w);
            As[nxt][lk0+4][lrow]=tf32r(pa1.x); As[nxt][lk0+5][lrow]=tf32r(pa1.y);
            As[nxt][lk0+6][lrow]=tf32r(pa1.z); As[nxt][lk0+7][lrow]=tf32r(pa1.w);
            Bs[nxt][lk0+0][lrow]=tf32r(pb0.x); Bs[nxt][lk0+1][lrow]=tf32r(pb0.y);
            Bs[nxt][lk0+2][lrow]=tf32r(pb0.z); Bs[nxt][lk0+3][lrow]=tf32r(pb0.w);
            Bs[nxt][lk0+4][lrow]=tf32r(pb1.x); Bs[nxt][lk0+5][lrow]=tf32r(pb1.y);
            Bs[nxt][lk0+6][lrow]=tf32r(pb1.z); Bs[nxt][lk0+7][lrow]=tf32r(pb1.w);
        }
        __syncthreads();
    }

    // epilogue with bias
    #pragma unroll
    for (int mt = 0; mt < 2; mt++) {
        #pragma unroll
        for (int nt = 0; nt < 8; nt++) {
            const int row = block_m + m0 + mt * 16 + gid;
            const int col = block_n + n0w + nt * 8 + tig * 2;
            const float bx = bias[col], by = bias[col + 1];
            float2 v0 = { acc[mt][nt][0] + bx, acc[mt][nt][1] + by };
            float2 v1 = { acc[mt][nt][2] + bx, acc[mt][nt][3] + by };
            *(float2*)(C + (size_t)row * DMODEL + col)       = v0;
            *(float2*)(C + (size_t)(row + 8) * DMODEL + col) = v1;
        }
    }
}

// ---------------------------------------------------------------------------
// Flash attention with TF32 MMA.
// Block: 256 thr = 8 warps, each warp owns 16 query rows (128 q / block).
// Key tiles of 64 keys; K/V staged in smem (tf32), Q fragments in registers,
// P routed through per-warp smem slice (syncwarp only).
// ---------------------------------------------------------------------------
#define ATT_SMEM_BYTES ((64*68 + 64*72 + 128*68) * 4)   // 70656

__global__ __launch_bounds__(256) void attn_mma(
    const float* __restrict__ Qp, const float* __restrict__ Kp,
    const float* __restrict__ Vp, float* __restrict__ Ctx)
{
    extern __shared__ float sm[];
    float (*Ks)[68] = (float(*)[68])sm;                       // [key][dh]
    float (*Vs)[72] = (float(*)[72])(sm + 64 * 68);           // [key][dh]
    float (*Ps)[68] = (float(*)[68])(sm + 64 * 68 + 64 * 72); // [q][*] (Q stage / P)

    const int tid  = threadIdx.x;
    const int lane = tid & 31;
    const int warp = tid >> 5;        // 0..7
    const int gid  = lane >> 2;
    const int tig  = lane & 3;
    const int q0   = warp * 16;

    const int b     = blockIdx.z;
    const int h     = blockIdx.y;
    const int q_blk = blockIdx.x * 128;

    // ---- stage Q (scaled by 1/8, tf32-rounded) ----
    const float* qbase = Qp + ((size_t)(b * SEQ + q_blk)) * DMODEL + h * DHEAD;
    #pragma unroll
    for (int r = 0; r < 8; r++) {
        int li  = r * 256 + tid;
        int row = li >> 4;
        int f4  = (li & 15) * 4;
        float4 v = *(const float4*)(qbase + (size_t)row * DMODEL + f4);
        Ps[row][f4 + 0] = tf32r(v.x * 0.125f);
        Ps[row][f4 + 1] = tf32r(v.y * 0.125f);
        Ps[row][f4 + 2] = tf32r(v.z * 0.125f);
        Ps[row][f4 + 3] = tf32r(v.w * 0.125f);
    }
    __syncthreads();

    uint32_t aq[8][4];
    #pragma unroll
    for (int ks = 0; ks < 8; ks++) {
        aq[ks][0] = fu(Ps[q0 + gid    ][ks*8 + tig    ]);
        aq[ks][1] = fu(Ps[q0 + gid + 8][ks*8 + tig    ]);
        aq[ks][2] = fu(Ps[q0 + gid    ][ks*8 + tig + 4]);
        aq[ks][3] = fu(Ps[q0 + gid + 8][ks*8 + tig + 4]);
    }

    float o[8][4];
    #pragma unroll
    for (int dt = 0; dt < 8; dt++)
        #pragma unroll
        for (int r = 0; r < 4; r++) o[dt][r] = 0.f;
    float m0 = -1e30f, m1 = -1e30f, l0 = 0.f, l1 = 0.f;

    const float* kbase = Kp + ((size_t)b * SEQ) * DMODEL + h * DHEAD;
    const float* vbase = Vp + ((size_t)b * SEQ) * DMODEL + h * DHEAD;

    for (int kt = 0; kt < SEQ / 64; ++kt) {
        __syncthreads();   // previous tile fully consumed (also guards Q->P reuse)

        // ---- load K/V tile: 64 keys x 64 dh ----
        #pragma unroll
        for (int r = 0; r < 4; r++) {
            int li  = r * 256 + tid;
            int key = li >> 4;
            int f4  = (li & 15) * 4;
            const size_t off = (size_t)(kt * 64 + key) * DMODEL + f4;
            float4 kv = *(const float4*)(kbase + off);
            float4 vv = *(const float4*)(vbase + off);
            Ks[key][f4+0]=tf32r(kv.x); Ks[key][f4+1]=tf32r(kv.y);
            Ks[key][f4+2]=tf32r(kv.z); Ks[key][f4+3]=tf32r(kv.w);
            Vs[key][f4+0]=tf32r(vv.x); Vs[key][f4+1]=tf32r(vv.y);
            Vs[key][f4+2]=tf32r(vv.z); Vs[key][f4+3]=tf32r(vv.w);
        }
        __syncthreads();

        // ---- S = Q K^T (scaled) ----
        float s[8][4];
        #pragma unroll
        for (int nt = 0; nt < 8; nt++)
            #pragma unroll
            for (int r = 0; r < 4; r++) s[nt][r] = 0.f;

        #pragma unroll
        for (int ks = 0; ks < 8; ks++) {
            uint32_t bk[8][2];
            #pragma unroll
            for (int nt = 0; nt < 8; nt++) {
                bk[nt][0] = fu(Ks[nt*8 + gid][ks*8 + tig    ]);
                bk[nt][1] = fu(Ks[nt*8 + gid][ks*8 + tig + 4]);
            }
            #pragma unroll
            for (int nt = 0; nt < 8; nt++)
                mma8(s[nt], aq[ks], bk[nt]);
        }

        // ---- online softmax ----
        float mx0 = -1e30f, mx1 = -1e30f;
        #pragma unroll
        for (int nt = 0; nt < 8; nt++) {
            mx0 = fmaxf(mx0, fmaxf(s[nt][0], s[nt][1]));
            mx1 = fmaxf(mx1, fmaxf(s[nt][2], s[nt][3]));
        }
        mx0 = fmaxf(mx0, __shfl_xor_sync(0xffffffffu, mx0, 1));
        mx0 = fmaxf(mx0, __shfl_xor_sync(0xffffffffu, mx0, 2));
        mx1 = fmaxf(mx1, __shfl_xor_sync(0xffffffffu, mx1, 1));
        mx1 = fmaxf(mx1, __shfl_xor_sync(0xffffffffu, mx1, 2));

        const float nm0 = fmaxf(m0, mx0), nm1 = fmaxf(m1, mx1);
        const float c0 = __expf(m0 - nm0), c1 = __expf(m1 - nm1);
        m0 = nm0; m1 = nm1;

        float ls0 = 0.f, ls1 = 0.f;
        #pragma unroll
        for (int nt = 0; nt < 8; nt++) {
            s[nt][0] = __expf(s[nt][0] - m0);
            s[nt][1] = __expf(s[nt][1] - m0);
            s[nt][2] = __expf(s[nt][2] - m1);
            s[nt][3] = __expf(s[nt][3] - m1);
            ls0 += s[nt][0] + s[nt][1];
            ls1 += s[nt][2] + s[nt][3];
        }
        l0 = l0 * c0 + ls0;
        l1 = l1 * c1 + ls1;
        #pragma unroll
        for (int dt = 0; dt < 8; dt++) {
            o[dt][0] *= c0; o[dt][1] *= c0;
            o[dt][2] *= c1; o[dt][3] *= c1;
        }

        // ---- P -> smem (per-warp slice) ----
        #pragma unroll
        for (int nt = 0; nt < 8; nt++) {
            const int col = nt * 8 + tig * 2;
            Ps[q0 + gid    ][col    ] = tf32r(s[nt][0]);
            Ps[q0 + gid    ][col + 1] = tf32r(s[nt][1]);
            Ps[q0 + gid + 8][col    ] = tf32r(s[nt][2]);
            Ps[q0 + gid + 8][col + 1] = tf32r(s[nt][3]);
        }
        __syncwarp();

        // ---- O += P V ----
        #pragma unroll
        for (int ks = 0; ks < 8; ks++) {
            uint32_t ap[4];
            ap[0] = fu(Ps[q0 + gid    ][ks*8 + tig    ]);
            ap[1] = fu(Ps[q0 + gid + 8][ks*8 + tig    ]);
            ap[2] = fu(Ps[q0 + gid    ][ks*8 + tig + 4]);
            ap[3] = fu(Ps[q0 + gid + 8][ks*8 + tig + 4]);
            #pragma unroll
            for (int nt = 0; nt < 8; nt++) {
                uint32_t bv[2];
                bv[0] = fu(Vs[ks*8 + tig    ][nt*8 + gid]);
                bv[1] = fu(Vs[ks*8 + tig + 4][nt*8 + gid]);
                mma8(o[nt], ap, bv);
            }
        }
        __syncwarp();
    }

    // ---- finalize ----
    l0 += __shfl_xor_sync(0xffffffffu, l0, 1);
    l0 += __shfl_xor_sync(0xffffffffu, l0, 2);
    l1 += __shfl_xor_sync(0xffffffffu, l1, 1);
    l1 += __shfl_xor_sync(0xffffffffu, l1, 2);
    const float i0 = 1.f / l0, i1 = 1.f / l1;

    float* cp0 = Ctx + ((size_t)(b * SEQ + q_blk + q0 + gid)) * DMODEL + h * DHEAD;
    float* cp1 = cp0 + (size_t)8 * DMODEL;
    #pragma unroll
    for (int nt = 0; nt < 8; nt++) {
        const int col = nt * 8 + tig * 2;
        float2 v0 = { o[nt][0] * i0, o[nt][1] * i0 };
        float2 v1 = { o[nt][2] * i1, o[nt][3] * i1 };
        *(float2*)(cp0 + col) = v0;
        *(float2*)(cp1 + col) = v1;
    }
}

// ---------------------------------------------------------------------------
extern "C" void kernel_launch(void* const* d_in, const int* in_sizes, int n_in,
                              void* d_out, int out_size)
{
    const float* x  = (const float*)d_in[0];
    const float* Wq = (const float*)d_in[1];
    const float* bq = (const float*)d_in[2];
    const float* Wk = (const float*)d_in[3];
    const float* bk = (const float*)d_in[4];
    const float* Wv = (const float*)d_in[5];
    const float* bv = (const float*)d_in[6];
    const float* Wo = (const float*)d_in[7];
    const float* bo = (const float*)d_in[8];
    float* out = (float*)d_out;

    float *Qd, *Kd, *Vd, *Cd;
    cudaGetSymbolAddress((void**)&Qd, g_Q);
    cudaGetSymbolAddress((void**)&Kd, g_K);
    cudaGetSymbolAddress((void**)&Vd, g_V);
    cudaGetSymbolAddress((void**)&Cd, g_C);

    static bool attr_set = false;
    if (!attr_set) {
        cudaFuncSetAttribute(attn_mma,
                             cudaFuncAttributeMaxDynamicSharedMemorySize,
                             ATT_SMEM_BYTES);
        attr_set = true;
    }

    dim3 ggrid(DMODEL / 128, MTOT / 128);   // (8, 32)
    gemm_tf32<<<ggrid, 256>>>(x, Wq, bq, Qd);
    gemm_tf32<<<ggrid, 256>>>(x, Wk, bk, Kd);
    gemm_tf32<<<ggrid, 256>>>(x, Wv, bv, Vd);

    dim3 agrid(SEQ / 128, HEADS, BATCH);    // (16, 16, 2)
    attn_mma<<<agrid, 256, ATT_SMEM_BYTES>>>(Qd, Kd, Vd, Cd);

    gemm_tf32<<<ggrid, 256>>>(Cd, Wo, bo, out);
}

// round 3
// speedup vs baseline: 2.4367x; 1.2120x over previous
#include <cuda_runtime.h>
#include <cstdint>

#define BATCH   2
#define SEQ     2048
#define DMODEL  1024
#define HEADS   16
#define DHEAD   64
#define MTOT    (BATCH * SEQ)   // 4096

// Scratch (allocation-free rule: __device__ globals)
__device__ float g_Q[MTOT * DMODEL];
__device__ float g_K[MTOT * DMODEL];
__device__ float g_V[MTOT * DMODEL];
__device__ float g_C[MTOT * DMODEL];

// ---------------------------------------------------------------------------
// helpers
// ---------------------------------------------------------------------------
__device__ __forceinline__ float tf32r(float x) {
    uint32_t u;
    asm("cvt.rna.tf32.f32 %0, %1;" : "=r"(u) : "f"(x));
    return __uint_as_float(u);
}
__device__ __forceinline__ uint32_t fu(float x) { return __float_as_uint(x); }

// D += A * B  (m16n8k8, tf32, fp32 accum)
__device__ __forceinline__ void mma8(float* d, const uint32_t* a, const uint32_t* b) {
    asm volatile(
        "mma.sync.aligned.m16n8k8.row.col.f32.tf32.tf32.f32 "
        "{%0,%1,%2,%3}, {%4,%5,%6,%7}, {%8,%9}, {%0,%1,%2,%3};\n"
        : "+f"(d[0]), "+f"(d[1]), "+f"(d[2]), "+f"(d[3])
        : "r"(a[0]), "r"(a[1]), "r"(a[2]), "r"(a[3]), "r"(b[0]), "r"(b[1]));
}

// Fragment layout conventions (m16n8k8, thread = (gid = lane>>2, tig = lane&3)):
//   A frag (16x8): a0=(gid,tig) a1=(gid+8,tig) a2=(gid,tig+4) a3=(gid+8,tig+4)
//     element (r,c): lane = (r&7)*4 + (c&3),  reg = (r>=8) + 2*(c>=4)
//   B frag (8x8, k x n): b0=(k=tig,n=gid) b1=(k=tig+4,n=gid)
//     element (c,n):  lane = (n&7)*4 + (c&3),  reg = c>>2
//   C frag: c0=(gid,2tig) c1=(gid,2tig+1) c2,c3 = row+8

// ---------------------------------------------------------------------------
// TF32 GEMM:  C[M,N] = A[M,K] @ W[N,K]^T + bias[N]
// Block 128x128, BK=16 (2 k-slices of 8), 256 thr, warp tile 32x64.
// Operands staged in FRAGMENT-PACKED smem: consumer A loads = LDS.128,
// consumer B loads = LDS.64, conflict-free.
// ---------------------------------------------------------------------------
__global__ __launch_bounds__(256, 2) void gemm_tf32(
    const float* __restrict__ A, const float* __restrict__ W,
    const float* __restrict__ bias, float* __restrict__ C)
{
    __shared__ float Af[2][2][8][32][4];   // [buf][slice][mtile][lane][reg]
    __shared__ float Bf[2][2][16][32][2];  // [buf][slice][ntile][lane][reg]

    const int tid  = threadIdx.x;
    const int lane = tid & 31;
    const int warp = tid >> 5;
    const int gid  = lane >> 2;
    const int tig  = lane & 3;
    const int t0   = (warp >> 1) * 2;    // warp's first m16 tile
    const int nb0  = (warp & 1) * 8;     // warp's first n8 tile

    const int block_m = blockIdx.y * 128;
    const int block_n = blockIdx.x * 128;

    const int lrow = tid >> 1;           // 0..127
    const int sl   = tid & 1;            // k-slice 0/1

    const float* Aptr = A + (size_t)(block_m + lrow) * DMODEL + sl * 8;
    const float* Wptr = W + (size_t)(block_n + lrow) * DMODEL + sl * 8;

    // producer write coords
    const int a_t  = lrow >> 4;
    const int a_l0 = (lrow & 7) * 4;
    const int a_rh = (lrow >> 3) & 1;
    const int b_nt = lrow >> 3;
    const int b_l0 = (lrow & 7) * 4;

    float acc[2][8][4];
    #pragma unroll
    for (int mt = 0; mt < 2; mt++)
        #pragma unroll
        for (int nt = 0; nt < 8; nt++)
            #pragma unroll
            for (int r = 0; r < 4; r++) acc[mt][nt][r] = 0.f;

    // ---- prologue: stage tile 0 ----
    {
        float4 a0 = *(const float4*)(Aptr);
        float4 a1 = *(const float4*)(Aptr + 4);
        float4 b0 = *(const float4*)(Wptr);
        float4 b1 = *(const float4*)(Wptr + 4);
        float av[8] = {a0.x,a0.y,a0.z,a0.w,a1.x,a1.y,a1.z,a1.w};
        float bv[8] = {b0.x,b0.y,b0.z,b0.w,b1.x,b1.y,b1.z,b1.w};
        #pragma unroll
        for (int c = 0; c < 8; c++) {
            Af[0][sl][a_t][a_l0 + (c & 3)][a_rh + 2 * (c >> 2)] = tf32r(av[c]);
            Bf[0][sl][b_nt][b_l0 + (c & 3)][c >> 2]             = tf32r(bv[c]);
        }
    }
    __syncthreads();

    const int NK = DMODEL / 16;   // 64
    for (int kt = 0; kt < NK; ++kt) {
        const int cur = kt & 1;
        float4 pa0, pa1, pb0, pb1;
        if (kt < NK - 1) {
            const float* ap = Aptr + (kt + 1) * 16;
            const float* wp = Wptr + (kt + 1) * 16;
            pa0 = *(const float4*)(ap);
            pa1 = *(const float4*)(ap + 4);
            pb0 = *(const float4*)(wp);
            pb1 = *(const float4*)(wp + 4);
        }

        #pragma unroll
        for (int ks = 0; ks < 2; ++ks) {
            float4 fa0 = *(const float4*)Af[cur][ks][t0    ][lane];
            float4 fa1 = *(const float4*)Af[cur][ks][t0 + 1][lane];
            float2 fb[8];
            #pragma unroll
            for (int nt = 0; nt < 8; nt++)
                fb[nt] = *(const float2*)Bf[cur][ks][nb0 + nt][lane];
            #pragma unroll
            for (int nt = 0; nt < 8; nt++) {
                mma8(acc[0][nt], (const uint32_t*)&fa0, (const uint32_t*)&fb[nt]);
                mma8(acc[1][nt], (const uint32_t*)&fa1, (const uint32_t*)&fb[nt]);
            }
        }

        if (kt < NK - 1) {
            const int nxt = cur ^ 1;
            float av[8] = {pa0.x,pa0.y,pa0.z,pa0.w,pa1.x,pa1.y,pa1.z,pa1.w};
            float bv[8] = {pb0.x,pb0.y,pb0.z,pb0.w,pb1.x,pb1.y,pb1.z,pb1.w};
            #pragma unroll
            for (int c = 0; c < 8; c++) {
                Af[nxt][sl][a_t][a_l0 + (c & 3)][a_rh + 2 * (c >> 2)] = tf32r(av[c]);
                Bf[nxt][sl][b_nt][b_l0 + (c & 3)][c >> 2]             = tf32r(bv[c]);
            }
        }
        __syncthreads();
    }

    // ---- epilogue with bias ----
    const int m0  = (warp >> 1) * 32;
    const int n0w = (warp & 1) * 64;
    #pragma unroll
    for (int mt = 0; mt < 2; mt++) {
        #pragma unroll
        for (int nt = 0; nt < 8; nt++) {
            const int row = block_m + m0 + mt * 16 + gid;
            const int col = block_n + n0w + nt * 8 + tig * 2;
            const float bx = bias[col], by = bias[col + 1];
            float2 v0 = { acc[mt][nt][0] + bx, acc[mt][nt][1] + by };
            float2 v1 = { acc[mt][nt][2] + bx, acc[mt][nt][3] + by };
            *(float2*)(C + (size_t)row * DMODEL + col)       = v0;
            *(float2*)(C + (size_t)(row + 8) * DMODEL + col) = v1;
        }
    }
}

// ---------------------------------------------------------------------------
// Flash attention, TF32 MMA, fragment-packed smem for K, V and P.
// Block: 256 thr = 8 warps; warp owns 16 q rows (128 q / block).
// Key tiles of 64. Kf: B-frags for QK^T (k=dh, n=key). Vf: B-frags for PV
// (k=key, n=dh). Pf: A-frags for PV, written directly from the S accumulator.
// ---------------------------------------------------------------------------
// floats: Kf 4096 | Vf 4096 | Pf 8192 (aliased by Q stage 128*68=8704)
#define ATT_SMEM_FLOATS (4096 + 4096 + 8704)
#define ATT_SMEM_BYTES  (ATT_SMEM_FLOATS * 4)   // 67584

__global__ __launch_bounds__(256) void attn_mma(
    const float* __restrict__ Qp, const float* __restrict__ Kp,
    const float* __restrict__ Vp, float* __restrict__ Ctx)
{
    extern __shared__ float sm[];
    float* Kf = sm;              // [ks8][nt8][32][2]
    float* Vf = sm + 4096;       // [ks8][nt8][32][2]
    float* Pf = sm + 8192;       // [warp8][ks8][32][4]
    float* Qs = sm + 8192;       // alias: [128][68]

    const int tid  = threadIdx.x;
    const int lane = tid & 31;
    const int warp = tid >> 5;        // 0..7
    const int gid  = lane >> 2;
    const int tig  = lane & 3;
    const int q0   = warp * 16;

    const int b     = blockIdx.z;
    const int h     = blockIdx.y;
    const int q_blk = blockIdx.x * 128;

    // ---- stage Q (scaled by 1/8, tf32-rounded), pad-68 rows ----
    const float* qbase = Qp + ((size_t)(b * SEQ + q_blk)) * DMODEL + h * DHEAD;
    #pragma unroll
    for (int r = 0; r < 8; r++) {
        int li  = r * 256 + tid;
        int row = li >> 4;
        int f4  = (li & 15) * 4;
        float4 v = *(const float4*)(qbase + (size_t)row * DMODEL + f4);
        Qs[row * 68 + f4 + 0] = tf32r(v.x * 0.125f);
        Qs[row * 68 + f4 + 1] = tf32r(v.y * 0.125f);
        Qs[row * 68 + f4 + 2] = tf32r(v.z * 0.125f);
        Qs[row * 68 + f4 + 3] = tf32r(v.w * 0.125f);
    }
    __syncthreads();

    uint32_t aq[8][4];
    #pragma unroll
    for (int ks = 0; ks < 8; ks++) {
        aq[ks][0] = fu(Qs[(q0 + gid    ) * 68 + ks * 8 + tig    ]);
        aq[ks][1] = fu(Qs[(q0 + gid + 8) * 68 + ks * 8 + tig    ]);
        aq[ks][2] = fu(Qs[(q0 + gid    ) * 68 + ks * 8 + tig + 4]);
        aq[ks][3] = fu(Qs[(q0 + gid + 8) * 68 + ks * 8 + tig + 4]);
    }

    float o[8][4];
    #pragma unroll
    for (int dt = 0; dt < 8; dt++)
        #pragma unroll
        for (int r = 0; r < 4; r++) o[dt][r] = 0.f;
    float m0 = -1e30f, m1 = -1e30f, l0 = 0.f, l1 = 0.f;

    const float* kbase = Kp + ((size_t)b * SEQ) * DMODEL + h * DHEAD;
    const float* vbase = Vp + ((size_t)b * SEQ) * DMODEL + h * DHEAD;

    float* PfW = Pf + warp * 1024;   // this warp's A-frag region

    for (int kt = 0; kt < SEQ / 64; ++kt) {
        __syncthreads();   // prior tile fully consumed / Qs->Pf reuse safe

        // ---- stage K/V tile (64 keys x 64 dh) into fragment layout ----
        #pragma unroll
        for (int r = 0; r < 4; r++) {
            int li  = r * 256 + tid;
            int key = li >> 4;
            int f4  = (li & 15) * 4;      // dh base, multiple of 4
            const size_t off = (size_t)(kt * 64 + key) * DMODEL + f4;
            float4 kv = *(const float4*)(kbase + off);
            float4 vv = *(const float4*)(vbase + off);

            // K as B-frag for QK^T: k=dh, n=key
            {
                const int sK  = f4 >> 3;
                const int reg = (f4 >> 2) & 1;
                float* dst = Kf + (((sK * 8 + (key >> 3)) * 32 + (key & 7) * 4) << 1) + reg;
                dst[0] = tf32r(kv.x);
                dst[2] = tf32r(kv.y);
                dst[4] = tf32r(kv.z);
                dst[6] = tf32r(kv.w);
            }
            // V as B-frag for PV: k=key, n=dh
            {
                const int sV  = key >> 3;
                const int reg = (key >> 2) & 1;
                const int lb  = (f4 & 7) * 4 + (key & 3);
                float* dst = Vf + (((sV * 8 + (f4 >> 3)) * 32 + lb) << 1) + reg;
                dst[0]  = tf32r(vv.x);
                dst[8]  = tf32r(vv.y);   // lane +4 -> +8 floats
                dst[16] = tf32r(vv.z);
                dst[24] = tf32r(vv.w);
            }
        }
        __syncthreads();

        // ---- S = Q K^T ----
        float s[8][4];
        #pragma unroll
        for (int nt = 0; nt < 8; nt++)
            #pragma unroll
            for (int r = 0; r < 4; r++) s[nt][r] = 0.f;

        #pragma unroll
        for (int ks = 0; ks < 8; ks++) {
            float2 kb[8];
            #pragma unroll
            for (int nt = 0; nt < 8; nt++)
                kb[nt] = *(const float2*)(Kf + (((ks * 8 + nt) * 32 + lane) << 1));
            #pragma unroll
            for (int nt = 0; nt < 8; nt++)
                mma8(s[nt], aq[ks], (const uint32_t*)&kb[nt]);
        }

        // ---- online softmax ----
        float mx0 = -1e30f, mx1 = -1e30f;
        #pragma unroll
        for (int nt = 0; nt < 8; nt++) {
            mx0 = fmaxf(mx0, fmaxf(s[nt][0], s[nt][1]));
            mx1 = fmaxf(mx1, fmaxf(s[nt][2], s[nt][3]));
        }
        mx0 = fmaxf(mx0, __shfl_xor_sync(0xffffffffu, mx0, 1));
        mx0 = fmaxf(mx0, __shfl_xor_sync(0xffffffffu, mx0, 2));
        mx1 = fmaxf(mx1, __shfl_xor_sync(0xffffffffu, mx1, 1));
        mx1 = fmaxf(mx1, __shfl_xor_sync(0xffffffffu, mx1, 2));

        const float nm0 = fmaxf(m0, mx0), nm1 = fmaxf(m1, mx1);
        const float c0 = __expf(m0 - nm0), c1 = __expf(m1 - nm1);
        m0 = nm0; m1 = nm1;

        float ls0 = 0.f, ls1 = 0.f;
        #pragma unroll
        for (int nt = 0; nt < 8; nt++) {
            s[nt][0] = __expf(s[nt][0] - m0);
            s[nt][1] = __expf(s[nt][1] - m0);
            s[nt][2] = __expf(s[nt][2] - m1);
            s[nt][3] = __expf(s[nt][3] - m1);
            ls0 += s[nt][0] + s[nt][1];
            ls1 += s[nt][2] + s[nt][3];
        }
        l0 = l0 * c0 + ls0;
        l1 = l1 * c1 + ls1;
        #pragma unroll
        for (int dt = 0; dt < 8; dt++) {
            o[dt][0] *= c0; o[dt][1] *= c0;
            o[dt][2] *= c1; o[dt][3] *= c1;
        }

        // ---- P accumulator -> A-fragment smem (per-warp, warp-sync only) ----
        // S elem (q=gid{,+8}, c=2tig{,+1}) in key-block nt (= slice for PV).
        {
            const int lw0 = gid * 4 + (tig & 1) * 2;   // lane of (gid, 2tig)
            const int rb  = (tig >> 1) * 2;            // 2*(c>=4)
            #pragma unroll
            for (int nt = 0; nt < 8; nt++) {
                float* pw = PfW + (nt << 7);           // [nt][32][4]
                pw[(lw0    ) * 4 + rb    ] = tf32r(s[nt][0]);
                pw[(lw0 + 1) * 4 + rb    ] = tf32r(s[nt][1]);
                pw[(lw0    ) * 4 + rb + 1] = tf32r(s[nt][2]);
                pw[(lw0 + 1) * 4 + rb + 1] = tf32r(s[nt][3]);
            }
        }
        __syncwarp();

        // ---- O += P V ----
        #pragma unroll
        for (int ks = 0; ks < 8; ks++) {
            float4 ap4 = *(const float4*)(PfW + (ks << 7) + lane * 4);
            #pragma unroll
            for (int nt = 0; nt < 8; nt++) {
                float2 vb = *(const float2*)(Vf + (((ks * 8 + nt) * 32 + lane) << 1));
                mma8(o[nt], (const uint32_t*)&ap4, (const uint32_t*)&vb);
            }
        }
        __syncwarp();
    }

    // ---- finalize ----
    l0 += __shfl_xor_sync(0xffffffffu, l0, 1);
    l0 += __shfl_xor_sync(0xffffffffu, l0, 2);
    l1 += __shfl_xor_sync(0xffffffffu, l1, 1);
    l1 += __shfl_xor_sync(0xffffffffu, l1, 2);
    const float i0 = 1.f / l0, i1 = 1.f / l1;

    float* cp0 = Ctx + ((size_t)(b * SEQ + q_blk + q0 + gid)) * DMODEL + h * DHEAD;
    float* cp1 = cp0 + (size_t)8 * DMODEL;
    #pragma unroll
    for (int nt = 0; nt < 8; nt++) {
        const int col = nt * 8 + tig * 2;
        float2 v0 = { o[nt][0] * i0, o[nt][1] * i0 };
        float2 v1 = { o[nt][2] * i1, o[nt][3] * i1 };
        *(float2*)(cp0 + col) = v0;
        *(float2*)(cp1 + col) = v1;
    }
}

// ---------------------------------------------------------------------------
extern "C" void kernel_launch(void* const* d_in, const int* in_sizes, int n_in,
                              void* d_out, int out_size)
{
    const float* x  = (const float*)d_in[0];
    const float* Wq = (const float*)d_in[1];
    const float* bq = (const float*)d_in[2];
    const float* Wk = (const float*)d_in[3];
    const float* bk = (const float*)d_in[4];
    const float* Wv = (const float*)d_in[5];
    const float* bv = (const float*)d_in[6];
    const float* Wo = (const float*)d_in[7];
    const float* bo = (const float*)d_in[8];
    float* out = (float*)d_out;

    float *Qd, *Kd, *Vd, *Cd;
    cudaGetSymbolAddress((void**)&Qd, g_Q);
    cudaGetSymbolAddress((void**)&Kd, g_K);
    cudaGetSymbolAddress((void**)&Vd, g_V);
    cudaGetSymbolAddress((void**)&Cd, g_C);

    static bool attr_set = false;
    if (!attr_set) {
        cudaFuncSetAttribute(attn_mma,
                             cudaFuncAttributeMaxDynamicSharedMemorySize,
                             ATT_SMEM_BYTES);
        attr_set = true;
    }

    dim3 ggrid(DMODEL / 128, MTOT / 128);   // (8, 32)
    gemm_tf32<<<ggrid, 256>>>(x, Wq, bq, Qd);
    gemm_tf32<<<ggrid, 256>>>(x, Wk, bk, Kd);
    gemm_tf32<<<ggrid, 256>>>(x, Wv, bv, Vd);

    dim3 agrid(SEQ / 128, HEADS, BATCH);    // (16, 16, 2)
    attn_mma<<<agrid, 256, ATT_SMEM_BYTES>>>(Qd, Kd, Vd, Cd);

    gemm_tf32<<<ggrid, 256>>>(Cd, Wo, bo, out);
}

// round 4
// speedup vs baseline: 3.3379x; 1.3698x over previous
#include <cuda_runtime.h>
#include <cstdint>

#define BATCH   2
#define SEQ     2048
#define DMODEL  1024
#define HEADS   16
#define DHEAD   64
#define MTOT    (BATCH * SEQ)   // 4096

// Scratch (allocation-free rule: __device__ globals)
__device__ float g_Q[MTOT * DMODEL];
__device__ float g_K[MTOT * DMODEL];
__device__ float g_V[MTOT * DMODEL];
__device__ float g_C[MTOT * DMODEL];

// ---------------------------------------------------------------------------
// helpers
// ---------------------------------------------------------------------------
__device__ __forceinline__ float tf32r(float x) {
    uint32_t u;
    asm("cvt.rna.tf32.f32 %0, %1;" : "=r"(u) : "f"(x));
    return __uint_as_float(u);
}
__device__ __forceinline__ uint32_t fu(float x) { return __float_as_uint(x); }

// A-fragment slot swizzle: float offset for slot s (0..31), XOR key from slot
// bits 3-4 into offset bits 2-3. Preserves 16B alignment; consumer LDS.128
// stays sequential-per-phase (4 wavefronts, minimum).
__device__ __forceinline__ int psw(int s) {
    return (s * 4) ^ (((s >> 3) & 3) << 2);
}

// D += A * B  (m16n8k8, tf32, fp32 accum)
__device__ __forceinline__ void mma8(float* d, const uint32_t* a, const uint32_t* b) {
    asm volatile(
        "mma.sync.aligned.m16n8k8.row.col.f32.tf32.tf32.f32 "
        "{%0,%1,%2,%3}, {%4,%5,%6,%7}, {%8,%9}, {%0,%1,%2,%3};\n"
        : "+f"(d[0]), "+f"(d[1]), "+f"(d[2]), "+f"(d[3])
        : "r"(a[0]), "r"(a[1]), "r"(a[2]), "r"(a[3]), "r"(b[0]), "r"(b[1]));
}

// Fragment layout (m16n8k8, thread = (gid = lane>>2, tig = lane&3)):
//   A frag (16x8): element (r,c): slot = (r&7)*4 + (c&3), reg = (r>=8) + 2*(c>=4)
//   B frag (8x8, k x n): element (c,n): slot = (n&7)*4 + (c&3), reg = c>>2
//   C frag: c0=(gid,2tig) c1=(gid,2tig+1) c2,c3 = row+8
// A frags stored as [frag][psw(slot)+reg], stride 132 floats.
// B frags stored as [frag][slot*2+reg],  stride 66 floats.

// ---------------------------------------------------------------------------
// TF32 GEMM:  C[M,N] = A[M,K] @ W[N,K]^T + bias[N]
// Block 128x128, BK=16 (2 k-slices of 8), 256 thr, warp tile 32x64.
// ---------------------------------------------------------------------------
#define AF_STRIDE 132
#define BF_STRIDE 66

__global__ __launch_bounds__(256, 2) void gemm_tf32(
    const float* __restrict__ A, const float* __restrict__ W,
    const float* __restrict__ bias, float* __restrict__ C)
{
    // Af: per buf 16 frags (mtile*2 + sl), Bf: per buf 32 frags (ntile*2 + sl)
    __shared__ float Afs[2][16 * AF_STRIDE];   // 2*2112 floats
    __shared__ float Bfs[2][32 * BF_STRIDE];   // 2*2112 floats

    const int tid  = threadIdx.x;
    const int lane = tid & 31;
    const int warp = tid >> 5;
    const int gid  = lane >> 2;
    const int tig  = lane & 3;
    const int t0   = (warp >> 1) * 2;    // warp's first m16 tile
    const int nb0  = (warp & 1) * 8;     // warp's first n8 tile

    const int block_m = blockIdx.y * 128;
    const int block_n = blockIdx.x * 128;

    const int lrow = tid >> 1;           // 0..127
    const int sl   = tid & 1;            // k-slice 0/1

    const float* Aptr = A + (size_t)(block_m + lrow) * DMODEL + sl * 8;
    const float* Wptr = W + (size_t)(block_n + lrow) * DMODEL + sl * 8;

    // producer coords
    const int a_fr  = (lrow >> 4) * 2 + sl;        // A frag id
    const int a_sl0 = (lrow & 7) * 4;              // slot base (c&3 added per comp)
    const int a_rh  = (lrow >> 3) & 1;             // reg bit 0
    const int b_fr  = (lrow >> 3) * 2 + sl;        // B frag id
    const int b_sl0 = (lrow & 7) * 4;

    const int pswl = psw(lane);

    float acc[2][8][4];
    #pragma unroll
    for (int mt = 0; mt < 2; mt++)
        #pragma unroll
        for (int nt = 0; nt < 8; nt++)
            #pragma unroll
            for (int r = 0; r < 4; r++) acc[mt][nt][r] = 0.f;

    // ---- prologue: stage tile 0 ----
    {
        float4 a0 = *(const float4*)(Aptr);
        float4 a1 = *(const float4*)(Aptr + 4);
        float4 b0 = *(const float4*)(Wptr);
        float4 b1 = *(const float4*)(Wptr + 4);
        float av[8] = {a0.x,a0.y,a0.z,a0.w,a1.x,a1.y,a1.z,a1.w};
        float bv[8] = {b0.x,b0.y,b0.z,b0.w,b1.x,b1.y,b1.z,b1.w};
        float* Ad = &Afs[0][a_fr * AF_STRIDE];
        float* Bd = &Bfs[0][b_fr * BF_STRIDE];
        #pragma unroll
        for (int c = 0; c < 8; c++) {
            Ad[psw(a_sl0 + (c & 3)) + a_rh + 2 * (c >> 2)] = tf32r(av[c]);
            Bd[(b_sl0 + (c & 3)) * 2 + (c >> 2)]           = tf32r(bv[c]);
        }
    }
    __syncthreads();

    const int NK = DMODEL / 16;   // 64
    for (int kt = 0; kt < NK; ++kt) {
        const int cur = kt & 1;
        float4 pa0, pa1, pb0, pb1;
        if (kt < NK - 1) {
            const float* ap = Aptr + (kt + 1) * 16;
            const float* wp = Wptr + (kt + 1) * 16;
            pa0 = *(const float4*)(ap);
            pa1 = *(const float4*)(ap + 4);
            pb0 = *(const float4*)(wp);
            pb1 = *(const float4*)(wp + 4);
        }

        const float* AfB = Afs[cur];
        const float* BfB = Bfs[cur];
        #pragma unroll
        for (int ks = 0; ks < 2; ++ks) {
            float4 fa0 = *(const float4*)(AfB + ((t0    ) * 2 + ks) * AF_STRIDE + pswl);
            float4 fa1 = *(const float4*)(AfB + ((t0 + 1) * 2 + ks) * AF_STRIDE + pswl);
            float2 fb[8];
            #pragma unroll
            for (int nt = 0; nt < 8; nt++)
                fb[nt] = *(const float2*)(BfB + ((nb0 + nt) * 2 + ks) * BF_STRIDE + lane * 2);
            #pragma unroll
            for (int nt = 0; nt < 8; nt++) {
                mma8(acc[0][nt], (const uint32_t*)&fa0, (const uint32_t*)&fb[nt]);
                mma8(acc[1][nt], (const uint32_t*)&fa1, (const uint32_t*)&fb[nt]);
            }
        }

        if (kt < NK - 1) {
            const int nxt = cur ^ 1;
            float av[8] = {pa0.x,pa0.y,pa0.z,pa0.w,pa1.x,pa1.y,pa1.z,pa1.w};
            float bv[8] = {pb0.x,pb0.y,pb0.z,pb0.w,pb1.x,pb1.y,pb1.z,pb1.w};
            float* Ad = &Afs[nxt][a_fr * AF_STRIDE];
            float* Bd = &Bfs[nxt][b_fr * BF_STRIDE];
            #pragma unroll
            for (int c = 0; c < 8; c++) {
                Ad[psw(a_sl0 + (c & 3)) + a_rh + 2 * (c >> 2)] = tf32r(av[c]);
                Bd[(b_sl0 + (c & 3)) * 2 + (c >> 2)]           = tf32r(bv[c]);
            }
        }
        __syncthreads();
    }

    // ---- epilogue with bias ----
    const int m0  = (warp >> 1) * 32;
    const int n0w = (warp & 1) * 64;
    #pragma unroll
    for (int mt = 0; mt < 2; mt++) {
        #pragma unroll
        for (int nt = 0; nt < 8; nt++) {
            const int row = block_m + m0 + mt * 16 + gid;
            const int col = block_n + n0w + nt * 8 + tig * 2;
            const float bx = bias[col], by = bias[col + 1];
            float2 v0 = { acc[mt][nt][0] + bx, acc[mt][nt][1] + by };
            float2 v1 = { acc[mt][nt][2] + bx, acc[mt][nt][3] + by };
            *(float2*)(C + (size_t)row * DMODEL + col)       = v0;
            *(float2*)(C + (size_t)(row + 8) * DMODEL + col) = v1;
        }
    }
}

// ---------------------------------------------------------------------------
// Flash attention, TF32 MMA, swizzled fragment-packed smem for K, V and P.
// Block: 256 thr = 8 warps; warp owns 16 q rows (128 q / block).
// Kf frags [kt8*8+sK] stride 66 (B-frags for QK^T: k=dh, n=key)
// Vf frags [sV*8+ntV] stride 66 (B-frags for PV: k=key, n=dh)
// Pf frags per warp [ks] stride 132 (A-frags for PV, swizzled slots)
// ---------------------------------------------------------------------------
// floats: Kf 4224 | Vf 4224 | max(Pf 8*8*132=8448, Qs 128*68=8704)
#define ATT_KF_FLOATS  (64 * 66)
#define ATT_SMEM_FLOATS (ATT_KF_FLOATS * 2 + 8704)
#define ATT_SMEM_BYTES  (ATT_SMEM_FLOATS * 4)   // 68608

__global__ __launch_bounds__(256) void attn_mma(
    const float* __restrict__ Qp, const float* __restrict__ Kp,
    const float* __restrict__ Vp, float* __restrict__ Ctx)
{
    extern __shared__ float sm[];
    float* Kf = sm;                          // 64 frags x 66
    float* Vf = sm + ATT_KF_FLOATS;          // 64 frags x 66
    float* Pf = sm + ATT_KF_FLOATS * 2;      // [warp8][ks8 x 132]
    float* Qs = sm + ATT_KF_FLOATS * 2;      // alias: [128][68]

    const int tid  = threadIdx.x;
    const int lane = tid & 31;
    const int warp = tid >> 5;        // 0..7
    const int gid  = lane >> 2;
    const int tig  = lane & 3;
    const int q0   = warp * 16;
    const int pswl = psw(lane);

    const int b     = blockIdx.z;
    const int h     = blockIdx.y;
    const int q_blk = blockIdx.x * 128;

    // ---- stage Q (scaled by 1/8, tf32-rounded), pad-68 rows ----
    const float* qbase = Qp + ((size_t)(b * SEQ + q_blk)) * DMODEL + h * DHEAD;
    #pragma unroll
    for (int r = 0; r < 8; r++) {
        int li  = r * 256 + tid;
        int row = li >> 4;
        int f4  = (li & 15) * 4;
        float4 v = *(const float4*)(qbase + (size_t)row * DMODEL + f4);
        Qs[row * 68 + f4 + 0] = tf32r(v.x * 0.125f);
        Qs[row * 68 + f4 + 1] = tf32r(v.y * 0.125f);
        Qs[row * 68 + f4 + 2] = tf32r(v.z * 0.125f);
        Qs[row * 68 + f4 + 3] = tf32r(v.w * 0.125f);
    }
    __syncthreads();

    uint32_t aq[8][4];
    #pragma unroll
    for (int ks = 0; ks < 8; ks++) {
        aq[ks][0] = fu(Qs[(q0 + gid    ) * 68 + ks * 8 + tig    ]);
        aq[ks][1] = fu(Qs[(q0 + gid + 8) * 68 + ks * 8 + tig    ]);
        aq[ks][2] = fu(Qs[(q0 + gid    ) * 68 + ks * 8 + tig + 4]);
        aq[ks][3] = fu(Qs[(q0 + gid + 8) * 68 + ks * 8 + tig + 4]);
    }

    float o[8][4];
    #pragma unroll
    for (int dt = 0; dt < 8; dt++)
        #pragma unroll
        for (int r = 0; r < 4; r++) o[dt][r] = 0.f;
    float m0 = -1e30f, m1 = -1e30f, l0 = 0.f, l1 = 0.f;

    const float* kbase = Kp + ((size_t)b * SEQ) * DMODEL + h * DHEAD;
    const float* vbase = Vp + ((size_t)b * SEQ) * DMODEL + h * DHEAD;

    float* PfW = Pf + warp * (8 * 132);   // this warp's A-frag region

    for (int kt = 0; kt < SEQ / 64; ++kt) {
        __syncthreads();   // prior tile fully consumed / Qs->Pf reuse safe

        // ---- stage K/V tile (64 keys x 64 dh) into swizzled fragment layout ----
        #pragma unroll
        for (int r = 0; r < 4; r++) {
            int li  = r * 256 + tid;
            int key = li >> 4;
            int f4  = (li & 15) * 4;      // dh base, multiple of 4
            const size_t off = (size_t)(kt * 64 + key) * DMODEL + f4;
            float4 kv = *(const float4*)(kbase + off);
            float4 vv = *(const float4*)(vbase + off);

            // K as B-frag: frag = kt8*8 + sK, slot = (key&7)*4 + i, reg = (f4>>2)&1
            {
                const int sK = f4 >> 3;
                float* dk = Kf + ((key >> 3) * 8 + sK) * 66
                               + ((key & 7) * 4) * 2 + ((f4 >> 2) & 1);
                dk[0] = tf32r(kv.x);
                dk[2] = tf32r(kv.y);
                dk[4] = tf32r(kv.z);
                dk[6] = tf32r(kv.w);
            }
            // V as B-frag: frag = sV*8 + ntV, slot = ((f4&7)+i)*4 + (key&3), reg = (key>>2)&1
            {
                float* dv = Vf + ((key >> 3) * 8 + (f4 >> 3)) * 66
                               + ((f4 & 7) * 4 + (key & 3)) * 2 + ((key >> 2) & 1);
                dv[0]  = tf32r(vv.x);
                dv[8]  = tf32r(vv.y);
                dv[16] = tf32r(vv.z);
                dv[24] = tf32r(vv.w);
            }
        }
        __syncthreads();

        // ---- S = Q K^T ----
        float s[8][4];
        #pragma unroll
        for (int nt = 0; nt < 8; nt++)
            #pragma unroll
            for (int r = 0; r < 4; r++) s[nt][r] = 0.f;

        #pragma unroll
        for (int ks = 0; ks < 8; ks++) {
            float2 kb[8];
            #pragma unroll
            for (int nt = 0; nt < 8; nt++)
                kb[nt] = *(const float2*)(Kf + (nt * 8 + ks) * 66 + lane * 2);
            #pragma unroll
            for (int nt = 0; nt < 8; nt++)
                mma8(s[nt], aq[ks], (const uint32_t*)&kb[nt]);
        }

        // ---- online softmax ----
        float mx0 = -1e30f, mx1 = -1e30f;
        #pragma unroll
        for (int nt = 0; nt < 8; nt++) {
            mx0 = fmaxf(mx0, fmaxf(s[nt][0], s[nt][1]));
            mx1 = fmaxf(mx1, fmaxf(s[nt][2], s[nt][3]));
        }
        mx0 = fmaxf(mx0, __shfl_xor_sync(0xffffffffu, mx0, 1));
        mx0 = fmaxf(mx0, __shfl_xor_sync(0xffffffffu, mx0, 2));
        mx1 = fmaxf(mx1, __shfl_xor_sync(0xffffffffu, mx1, 1));
        mx1 = fmaxf(mx1, __shfl_xor_sync(0xffffffffu, mx1, 2));

        const float nm0 = fmaxf(m0, mx0), nm1 = fmaxf(m1, mx1);
        const float c0 = __expf(m0 - nm0), c1 = __expf(m1 - nm1);
        m0 = nm0; m1 = nm1;

        float ls0 = 0.f, ls1 = 0.f;
        #pragma unroll
        for (int nt = 0; nt < 8; nt++) {
            s[nt][0] = __expf(s[nt][0] - m0);
            s[nt][1] = __expf(s[nt][1] - m0);
            s[nt][2] = __expf(s[nt][2] - m1);
            s[nt][3] = __expf(s[nt][3] - m1);
            ls0 += s[nt][0] + s[nt][1];
            ls1 += s[nt][2] + s[nt][3];
        }
        l0 = l0 * c0 + ls0;
        l1 = l1 * c1 + ls1;
        #pragma unroll
        for (int dt = 0; dt < 8; dt++) {
            o[dt][0] *= c0; o[dt][1] *= c0;
            o[dt][2] *= c1; o[dt][3] *= c1;
        }

        // ---- P accumulator -> swizzled A-fragment smem (per-warp) ----
        {
            const int sl0 = gid * 4 + (tig & 1) * 2;   // slot of (gid, 2tig)
            const int rb  = (tig >> 1) * 2;            // 2*(c>=4)
            const int p0  = psw(sl0);
            const int p1  = psw(sl0 + 1);
            #pragma unroll
            for (int nt = 0; nt < 8; nt++) {
                float* pw = PfW + nt * 132;
                pw[p0 + rb    ] = tf32r(s[nt][0]);
                pw[p1 + rb    ] = tf32r(s[nt][1]);
                pw[p0 + rb + 1] = tf32r(s[nt][2]);
                pw[p1 + rb + 1] = tf32r(s[nt][3]);
            }
        }
        __syncwarp();

        // ---- O += P V ----
        #pragma unroll
        for (int ks = 0; ks < 8; ks++) {
            float4 ap4 = *(const float4*)(PfW + ks * 132 + pswl);
            #pragma unroll
            for (int nt = 0; nt < 8; nt++) {
                float2 vb = *(const float2*)(Vf + (ks * 8 + nt) * 66 + lane * 2);
                mma8(o[nt], (const uint32_t*)&ap4, (const uint32_t*)&vb);
            }
        }
        __syncwarp();
    }

    // ---- finalize ----
    l0 += __shfl_xor_sync(0xffffffffu, l0, 1);
    l0 += __shfl_xor_sync(0xffffffffu, l0, 2);
    l1 += __shfl_xor_sync(0xffffffffu, l1, 1);
    l1 += __shfl_xor_sync(0xffffffffu, l1, 2);
    const float i0 = 1.f / l0, i1 = 1.f / l1;

    float* cp0 = Ctx + ((size_t)(b * SEQ + q_blk + q0 + gid)) * DMODEL + h * DHEAD;
    float* cp1 = cp0 + (size_t)8 * DMODEL;
    #pragma unroll
    for (int nt = 0; nt < 8; nt++) {
        const int col = nt * 8 + tig * 2;
        float2 v0 = { o[nt][0] * i0, o[nt][1] * i0 };
        float2 v1 = { o[nt][2] * i1, o[nt][3] * i1 };
        *(float2*)(cp0 + col) = v0;
        *(float2*)(cp1 + col) = v1;
    }
}

// ---------------------------------------------------------------------------
extern "C" void kernel_launch(void* const* d_in, const int* in_sizes, int n_in,
                              void* d_out, int out_size)
{
    const float* x  = (const float*)d_in[0];
    const float* Wq = (const float*)d_in[1];
    const float* bq = (const float*)d_in[2];
    const float* Wk = (const float*)d_in[3];
    const float* bk = (const float*)d_in[4];
    const float* Wv = (const float*)d_in[5];
    const float* bv = (const float*)d_in[6];
    const float* Wo = (const float*)d_in[7];
    const float* bo = (const float*)d_in[8];
    float* out = (float*)d_out;

    float *Qd, *Kd, *Vd, *Cd;
    cudaGetSymbolAddress((void**)&Qd, g_Q);
    cudaGetSymbolAddress((void**)&Kd, g_K);
    cudaGetSymbolAddress((void**)&Vd, g_V);
    cudaGetSymbolAddress((void**)&Cd, g_C);

    static bool attr_set = false;
    if (!attr_set) {
        cudaFuncSetAttribute(attn_mma,
                             cudaFuncAttributeMaxDynamicSharedMemorySize,
                             ATT_SMEM_BYTES);
        attr_set = true;
    }

    dim3 ggrid(DMODEL / 128, MTOT / 128);   // (8, 32)
    gemm_tf32<<<ggrid, 256>>>(x, Wq, bq, Qd);
    gemm_tf32<<<ggrid, 256>>>(x, Wk, bk, Kd);
    gemm_tf32<<<ggrid, 256>>>(x, Wv, bv, Vd);

    dim3 agrid(SEQ / 128, HEADS, BATCH);    // (16, 16, 2)
    attn_mma<<<agrid, 256, ATT_SMEM_BYTES>>>(Qd, Kd, Vd, Cd);

    gemm_tf32<<<ggrid, 256>>>(Cd, Wo, bo, out);
}

// round 6
// speedup vs baseline: 3.6418x; 1.0911x over previous
#include <cuda_runtime.h>
#include <cstdint>

#define BATCH   2
#define SEQ     2048
#define DMODEL  1024
#define HEADS   16
#define DHEAD   64
#define MTOT    (BATCH * SEQ)   // 4096

// Scratch (allocation-free rule: __device__ globals)
__device__ float g_Q[MTOT * DMODEL];
__device__ float g_K[MTOT * DMODEL];
__device__ float g_V[MTOT * DMODEL];
__device__ float g_C[MTOT * DMODEL];

// ---------------------------------------------------------------------------
// helpers
// ---------------------------------------------------------------------------
__device__ __forceinline__ float tf32r(float x) {
    uint32_t u;
    asm("cvt.rna.tf32.f32 %0, %1;" : "=r"(u) : "f"(x));
    return __uint_as_float(u);
}
__device__ __forceinline__ uint32_t fu(float x) { return __float_as_uint(x); }

// A-fragment slot swizzle: float offset for slot s (0..31), XOR key from slot
// bits 3-4 into offset bits 2-3. Preserves 16B alignment.
__device__ __forceinline__ int psw(int s) {
    return (s * 4) ^ (((s >> 3) & 3) << 2);
}

// D += A * B  (m16n8k8, tf32, fp32 accum)
__device__ __forceinline__ void mma8(float* d, const uint32_t* a, const uint32_t* b) {
    asm volatile(
        "mma.sync.aligned.m16n8k8.row.col.f32.tf32.tf32.f32 "
        "{%0,%1,%2,%3}, {%4,%5,%6,%7}, {%8,%9}, {%0,%1,%2,%3};\n"
        : "+f"(d[0]), "+f"(d[1]), "+f"(d[2]), "+f"(d[3])
        : "r"(a[0]), "r"(a[1]), "r"(a[2]), "r"(a[3]), "r"(b[0]), "r"(b[1]));
}

// Fragment layout (m16n8k8, thread = (gid = lane>>2, tig = lane&3)):
//   A frag (16x8): element (r,c): slot = (r&7)*4 + (c&3), reg = (r>=8) + 2*(c>=4)
//   B frag (8x8, k x n): element (c,n): slot = (n&7)*4 + (c&3), reg = c>>2
//   C frag: c0=(gid,2tig) c1=(gid,2tig+1) c2,c3 = row+8
// A frags: [frag][psw(slot)+reg], stride 132. B frags: [frag][slot*2+reg], stride 66.

// ---------------------------------------------------------------------------
// TF32 GEMM:  C[M,N] = A[M,K] @ W[N,K]^T + bias[N]   (unchanged from R4)
// ---------------------------------------------------------------------------
#define AF_STRIDE 132
#define BF_STRIDE 66

__global__ __launch_bounds__(256, 2) void gemm_tf32(
    const float* __restrict__ A, const float* __restrict__ W,
    const float* __restrict__ bias, float* __restrict__ C)
{
    __shared__ float Afs[2][16 * AF_STRIDE];
    __shared__ float Bfs[2][32 * BF_STRIDE];

    const int tid  = threadIdx.x;
    const int lane = tid & 31;
    const int warp = tid >> 5;
    const int gid  = lane >> 2;
    const int tig  = lane & 3;
    const int t0   = (warp >> 1) * 2;
    const int nb0  = (warp & 1) * 8;

    const int block_m = blockIdx.y * 128;
    const int block_n = blockIdx.x * 128;

    const int lrow = tid >> 1;
    const int sl   = tid & 1;

    const float* Aptr = A + (size_t)(block_m + lrow) * DMODEL + sl * 8;
    const float* Wptr = W + (size_t)(block_n + lrow) * DMODEL + sl * 8;

    const int a_fr  = (lrow >> 4) * 2 + sl;
    const int a_sl0 = (lrow & 7) * 4;
    const int a_rh  = (lrow >> 3) & 1;
    const int b_fr  = (lrow >> 3) * 2 + sl;
    const int b_sl0 = (lrow & 7) * 4;

    const int pswl = psw(lane);

    float acc[2][8][4];
    #pragma unroll
    for (int mt = 0; mt < 2; mt++)
        #pragma unroll
        for (int nt = 0; nt < 8; nt++)
            #pragma unroll
            for (int r = 0; r < 4; r++) acc[mt][nt][r] = 0.f;

    {
        float4 a0 = *(const float4*)(Aptr);
        float4 a1 = *(const float4*)(Aptr + 4);
        float4 b0 = *(const float4*)(Wptr);
        float4 b1 = *(const float4*)(Wptr + 4);
        float av[8] = {a0.x,a0.y,a0.z,a0.w,a1.x,a1.y,a1.z,a1.w};
        float bv[8] = {b0.x,b0.y,b0.z,b0.w,b1.x,b1.y,b1.z,b1.w};
        float* Ad = &Afs[0][a_fr * AF_STRIDE];
        float* Bd = &Bfs[0][b_fr * BF_STRIDE];
        #pragma unroll
        for (int c = 0; c < 8; c++) {
            Ad[psw(a_sl0 + (c & 3)) + a_rh + 2 * (c >> 2)] = tf32r(av[c]);
            Bd[(b_sl0 + (c & 3)) * 2 + (c >> 2)]           = tf32r(bv[c]);
        }
    }
    __syncthreads();

    const int NK = DMODEL / 16;   // 64
    for (int kt = 0; kt < NK; ++kt) {
        const int cur = kt & 1;
        float4 pa0, pa1, pb0, pb1;
        if (kt < NK - 1) {
            const float* ap = Aptr + (kt + 1) * 16;
            const float* wp = Wptr + (kt + 1) * 16;
            pa0 = *(const float4*)(ap);
            pa1 = *(const float4*)(ap + 4);
            pb0 = *(const float4*)(wp);
            pb1 = *(const float4*)(wp + 4);
        }

        const float* AfB = Afs[cur];
        const float* BfB = Bfs[cur];
        #pragma unroll
        for (int ks = 0; ks < 2; ++ks) {
            float4 fa0 = *(const float4*)(AfB + ((t0    ) * 2 + ks) * AF_STRIDE + pswl);
            float4 fa1 = *(const float4*)(AfB + ((t0 + 1) * 2 + ks) * AF_STRIDE + pswl);
            float2 fb[8];
            #pragma unroll
            for (int nt = 0; nt < 8; nt++)
                fb[nt] = *(const float2*)(BfB + ((nb0 + nt) * 2 + ks) * BF_STRIDE + lane * 2);
            #pragma unroll
            for (int nt = 0; nt < 8; nt++) {
                mma8(acc[0][nt], (const uint32_t*)&fa0, (const uint32_t*)&fb[nt]);
                mma8(acc[1][nt], (const uint32_t*)&fa1, (const uint32_t*)&fb[nt]);
            }
        }

        if (kt < NK - 1) {
            const int nxt = cur ^ 1;
            float av[8] = {pa0.x,pa0.y,pa0.z,pa0.w,pa1.x,pa1.y,pa1.z,pa1.w};
            float bv[8] = {pb0.x,pb0.y,pb0.z,pb0.w,pb1.x,pb1.y,pb1.z,pb1.w};
            float* Ad = &Afs[nxt][a_fr * AF_STRIDE];
            float* Bd = &Bfs[nxt][b_fr * BF_STRIDE];
            #pragma unroll
            for (int c = 0; c < 8; c++) {
                Ad[psw(a_sl0 + (c & 3)) + a_rh + 2 * (c >> 2)] = tf32r(av[c]);
                Bd[(b_sl0 + (c & 3)) * 2 + (c >> 2)]           = tf32r(bv[c]);
            }
        }
        __syncthreads();
    }

    const int m0  = (warp >> 1) * 32;
    const int n0w = (warp & 1) * 64;
    #pragma unroll
    for (int mt = 0; mt < 2; mt++) {
        #pragma unroll
        for (int nt = 0; nt < 8; nt++) {
            const int row = block_m + m0 + mt * 16 + gid;
            const int col = block_n + n0w + nt * 8 + tig * 2;
            const float bx = bias[col], by = bias[col + 1];
            float2 v0 = { acc[mt][nt][0] + bx, acc[mt][nt][1] + by };
            float2 v1 = { acc[mt][nt][2] + bx, acc[mt][nt][3] + by };
            *(float2*)(C + (size_t)row * DMODEL + col)       = v0;
            *(float2*)(C + (size_t)(row + 8) * DMODEL + col) = v1;
        }
    }
}

// ---------------------------------------------------------------------------
// Flash attention, TF32 MMA, swizzled fragment-packed smem.
// Block: 256 thr = 8 warps; warp owns 16 q rows (128 q / block).
// KEY TILE = 128 keys staged at once; softmax/PV in two 64-key sub-rounds.
// Kf frags [key8*8+sK] stride 66;  Vf frags [sV*8+ntV] stride 66 (sV=key>>3)
// Pf per warp: 8 A-frags stride 132 (swizzled slots), reused per sub-round.
// __launch_bounds__(256,2): cap 128 regs -> 2 CTAs/SM.
// ---------------------------------------------------------------------------
#define ATT_KF_FLOATS  (128 * 66)                      // 8448
#define ATT_SMEM_FLOATS (ATT_KF_FLOATS * 2 + 8704)     // 25600
#define ATT_SMEM_BYTES  (ATT_SMEM_FLOATS * 4)          // 102400

__global__ __launch_bounds__(256, 2) void attn_mma(
    const float* __restrict__ Qp, const float* __restrict__ Kp,
    const float* __restrict__ Vp, float* __restrict__ Ctx)
{
    extern __shared__ float sm[];
    float* Kf = sm;                          // 128 frags x 66
    float* Vf = sm + ATT_KF_FLOATS;          // 128 frags x 66
    float* Pf = sm + ATT_KF_FLOATS * 2;      // [warp8][ks8 x 132]
    float* Qs = sm + ATT_KF_FLOATS * 2;      // alias: [128][68]

    const int tid  = threadIdx.x;
    const int lane = tid & 31;
    const int warp = tid >> 5;
    const int gid  = lane >> 2;
    const int tig  = lane & 3;
    const int q0   = warp * 16;
    const int pswl = psw(lane);

    const int b     = blockIdx.z;
    const int h     = blockIdx.y;
    const int q_blk = blockIdx.x * 128;

    // ---- stage Q (scaled by 1/8, tf32-rounded), pad-68 rows ----
    const float* qbase = Qp + ((size_t)(b * SEQ + q_blk)) * DMODEL + h * DHEAD;
    #pragma unroll
    for (int r = 0; r < 8; r++) {
        int li  = r * 256 + tid;
        int row = li >> 4;
        int f4  = (li & 15) * 4;
        float4 v = *(const float4*)(qbase + (size_t)row * DMODEL + f4);
        Qs[row * 68 + f4 + 0] = tf32r(v.x * 0.125f);
        Qs[row * 68 + f4 + 1] = tf32r(v.y * 0.125f);
        Qs[row * 68 + f4 + 2] = tf32r(v.z * 0.125f);
        Qs[row * 68 + f4 + 3] = tf32r(v.w * 0.125f);
    }
    __syncthreads();

    uint32_t aq[8][4];
    #pragma unroll
    for (int ks = 0; ks < 8; ks++) {
        aq[ks][0] = fu(Qs[(q0 + gid    ) * 68 + ks * 8 + tig    ]);
        aq[ks][1] = fu(Qs[(q0 + gid + 8) * 68 + ks * 8 + tig    ]);
        aq[ks][2] = fu(Qs[(q0 + gid    ) * 68 + ks * 8 + tig + 4]);
        aq[ks][3] = fu(Qs[(q0 + gid + 8) * 68 + ks * 8 + tig + 4]);
    }

    float o[8][4];
    #pragma unroll
    for (int dt = 0; dt < 8; dt++)
        #pragma unroll
        for (int r = 0; r < 4; r++) o[dt][r] = 0.f;
    float m0 = -1e30f, m1 = -1e30f, l0 = 0.f, l1 = 0.f;

    const float* kbase = Kp + ((size_t)b * SEQ) * DMODEL + h * DHEAD;
    const float* vbase = Vp + ((size_t)b * SEQ) * DMODEL + h * DHEAD;

    float* PfW = Pf + warp * (8 * 132);

    for (int kt = 0; kt < SEQ / 128; ++kt) {
        __syncthreads();   // prior tile fully consumed / Qs->Pf reuse safe

        // ---- stage 128 keys x 64 dh into swizzled fragment layout ----
        #pragma unroll
        for (int r = 0; r < 8; r++) {
            int li  = r * 256 + tid;
            int key = li >> 4;            // 0..127
            int f4  = (li & 15) * 4;
            const size_t off = (size_t)(kt * 128 + key) * DMODEL + f4;
            float4 kv = *(const float4*)(kbase + off);
            float4 vv = *(const float4*)(vbase + off);

            {   // K B-frag: frag = (key>>3)*8 + sK
                const int sK = f4 >> 3;
                float* dk = Kf + ((key >> 3) * 8 + sK) * 66
                               + ((key & 7) * 4) * 2 + ((f4 >> 2) & 1);
                dk[0] = tf32r(kv.x);
                dk[2] = tf32r(kv.y);
                dk[4] = tf32r(kv.z);
                dk[6] = tf32r(kv.w);
            }
            {   // V B-frag: frag = (key>>3)*8 + (f4>>3)
                float* dv = Vf + ((key >> 3) * 8 + (f4 >> 3)) * 66
                               + ((f4 & 7) * 4 + (key & 3)) * 2 + ((key >> 2) & 1);
                dv[0]  = tf32r(vv.x);
                dv[8]  = tf32r(vv.y);
                dv[16] = tf32r(vv.z);
                dv[24] = tf32r(vv.w);
            }
        }
        __syncthreads();

        // ---- two 64-key sub-rounds over the staged 128 keys ----
        #pragma unroll
        for (int hf = 0; hf < 2; ++hf) {
            const float* KfH = Kf + hf * (8 * 8 * 66);
            const float* VfH = Vf + hf * (8 * 8 * 66);

            float s[8][4];
            #pragma unroll
            for (int nt = 0; nt < 8; nt++)
                #pragma unroll
                for (int r = 0; r < 4; r++) s[nt][r] = 0.f;

            #pragma unroll
            for (int ks = 0; ks < 8; ks++) {
                float2 kb[8];
                #pragma unroll
                for (int nt = 0; nt < 8; nt++)
                    kb[nt] = *(const float2*)(KfH + (nt * 8 + ks) * 66 + lane * 2);
                #pragma unroll
                for (int nt = 0; nt < 8; nt++)
                    mma8(s[nt], aq[ks], (const uint32_t*)&kb[nt]);
            }

            // online softmax
            float mx0 = -1e30f, mx1 = -1e30f;
            #pragma unroll
            for (int nt = 0; nt < 8; nt++) {
                mx0 = fmaxf(mx0, fmaxf(s[nt][0], s[nt][1]));
                mx1 = fmaxf(mx1, fmaxf(s[nt][2], s[nt][3]));
            }
            mx0 = fmaxf(mx0, __shfl_xor_sync(0xffffffffu, mx0, 1));
            mx0 = fmaxf(mx0, __shfl_xor_sync(0xffffffffu, mx0, 2));
            mx1 = fmaxf(mx1, __shfl_xor_sync(0xffffffffu, mx1, 1));
            mx1 = fmaxf(mx1, __shfl_xor_sync(0xffffffffu, mx1, 2));

            const float nm0 = fmaxf(m0, mx0), nm1 = fmaxf(m1, mx1);
            const float c0 = __expf(m0 - nm0), c1 = __expf(m1 - nm1);
            m0 = nm0; m1 = nm1;

            float ls0 = 0.f, ls1 = 0.f;
            #pragma unroll
            for (int nt = 0; nt < 8; nt++) {
                s[nt][0] = __expf(s[nt][0] - m0);
                s[nt][1] = __expf(s[nt][1] - m0);
                s[nt][2] = __expf(s[nt][2] - m1);
                s[nt][3] = __expf(s[nt][3] - m1);
                ls0 += s[nt][0] + s[nt][1];
                ls1 += s[nt][2] + s[nt][3];
            }
            l0 = l0 * c0 + ls0;
            l1 = l1 * c1 + ls1;
            #pragma unroll
            for (int dt = 0; dt < 8; dt++) {
                o[dt][0] *= c0; o[dt][1] *= c0;
                o[dt][2] *= c1; o[dt][3] *= c1;
            }

            // P accumulator -> swizzled A-fragment smem (per-warp)
            {
                const int sl0 = gid * 4 + (tig & 1) * 2;
                const int rb  = (tig >> 1) * 2;
                const int p0  = psw(sl0);
                const int p1  = psw(sl0 + 1);
                #pragma unroll
                for (int nt = 0; nt < 8; nt++) {
                    float* pw = PfW + nt * 132;
                    pw[p0 + rb    ] = tf32r(s[nt][0]);
                    pw[p1 + rb    ] = tf32r(s[nt][1]);
                    pw[p0 + rb + 1] = tf32r(s[nt][2]);
                    pw[p1 + rb + 1] = tf32r(s[nt][3]);
                }
            }
            __syncwarp();

            // O += P V
            #pragma unroll
            for (int ks = 0; ks < 8; ks++) {
                float4 ap4 = *(const float4*)(PfW + ks * 132 + pswl);
                #pragma unroll
                for (int nt = 0; nt < 8; nt++) {
                    float2 vb = *(const float2*)(VfH + (ks * 8 + nt) * 66 + lane * 2);
                    mma8(o[nt], (const uint32_t*)&ap4, (const uint32_t*)&vb);
                }
            }
            __syncwarp();
        }
    }

    // ---- finalize ----
    l0 += __shfl_xor_sync(0xffffffffu, l0, 1);
    l0 += __shfl_xor_sync(0xffffffffu, l0, 2);
    l1 += __shfl_xor_sync(0xffffffffu, l1, 1);
    l1 += __shfl_xor_sync(0xffffffffu, l1, 2);
    const float i0 = 1.f / l0, i1 = 1.f / l1;

    float* cp0 = Ctx + ((size_t)(b * SEQ + q_blk + q0 + gid)) * DMODEL + h * DHEAD;
    float* cp1 = cp0 + (size_t)8 * DMODEL;
    #pragma unroll
    for (int nt = 0; nt < 8; nt++) {
        const int col = nt * 8 + tig * 2;
        float2 v0 = { o[nt][0] * i0, o[nt][1] * i0 };
        float2 v1 = { o[nt][2] * i1, o[nt][3] * i1 };
        *(float2*)(cp0 + col) = v0;
        *(float2*)(cp1 + col) = v1;
    }
}

// ---------------------------------------------------------------------------
extern "C" void kernel_launch(void* const* d_in, const int* in_sizes, int n_in,
                              void* d_out, int out_size)
{
    const float* x  = (const float*)d_in[0];
    const float* Wq = (const float*)d_in[1];
    const float* bq = (const float*)d_in[2];
    const float* Wk = (const float*)d_in[3];
    const float* bk = (const float*)d_in[4];
    const float* Wv = (const float*)d_in[5];
    const float* bv = (const float*)d_in[6];
    const float* Wo = (const float*)d_in[7];
    const float* bo = (const float*)d_in[8];
    float* out = (float*)d_out;

    float *Qd, *Kd, *Vd, *Cd;
    cudaGetSymbolAddress((void**)&Qd, g_Q);
    cudaGetSymbolAddress((void**)&Kd, g_K);
    cudaGetSymbolAddress((void**)&Vd, g_V);
    cudaGetSymbolAddress((void**)&Cd, g_C);

    static bool attr_set = false;
    if (!attr_set) {
        cudaFuncSetAttribute(attn_mma,
                             cudaFuncAttributeMaxDynamicSharedMemorySize,
                             ATT_SMEM_BYTES);
        attr_set = true;
    }

    dim3 ggrid(DMODEL / 128, MTOT / 128);   // (8, 32)
    gemm_tf32<<<ggrid, 256>>>(x, Wq, bq, Qd);
    gemm_tf32<<<ggrid, 256>>>(x, Wk, bk, Kd);
    gemm_tf32<<<ggrid, 256>>>(x, Wv, bv, Vd);

    dim3 agrid(SEQ / 128, HEADS, BATCH);    // (16, 16, 2)
    attn_mma<<<agrid, 256, ATT_SMEM_BYTES>>>(Qd, Kd, Vd, Cd);

    gemm_tf32<<<ggrid, 256>>>(Cd, Wo, bo, out);
}

// round 8
// speedup vs baseline: 5.7454x; 1.5776x over previous
#include <cuda_runtime.h>
#include <cuda_fp16.h>
#include <cstdint>

#define BATCH   2
#define SEQ     2048
#define DMODEL  1024
#define HEADS   16
#define DHEAD   64
#define MTOT    (BATCH * SEQ)   // 4096

// Scratch (allocation-free rule: __device__ globals)
__device__ float g_Q[MTOT * DMODEL];
__device__ float g_K[MTOT * DMODEL];
__device__ float g_V[MTOT * DMODEL];
__device__ float g_C[MTOT * DMODEL];

// ---------------------------------------------------------------------------
// helpers
// ---------------------------------------------------------------------------
__device__ __forceinline__ uint32_t f2h2(float lo, float hi) {
    __half2 h = __floats2half2_rn(lo, hi);   // lo -> .x (low half)
    return *(uint32_t*)&h;
}
__device__ __forceinline__ float ex2f(float x) {
    float y;
    asm("ex2.approx.ftz.f32 %0, %1;" : "=f"(y) : "f"(x));
    return y;
}
// A-fragment slot swizzle: float-offset for slot s, XOR of slot bits 3-4 into
// offset bits 2-3. Preserves 16B alignment for consumer LDS.128.
__device__ __forceinline__ int psw(int s) {
    return (s * 4) ^ (((s >> 3) & 3) << 2);
}
// D += A * B  (m16n8k16, fp16 in, fp32 accum)
__device__ __forceinline__ void mma16(float* d, const uint32_t* a, const uint32_t* b) {
    asm volatile(
        "mma.sync.aligned.m16n8k16.row.col.f32.f16.f16.f32 "
        "{%0,%1,%2,%3}, {%4,%5,%6,%7}, {%8,%9}, {%0,%1,%2,%3};\n"
        : "+f"(d[0]), "+f"(d[1]), "+f"(d[2]), "+f"(d[3])
        : "r"(a[0]), "r"(a[1]), "r"(a[2]), "r"(a[3]), "r"(b[0]), "r"(b[1]));
}

// Fragment layout (m16n8k16, thread = (gid = lane>>2, tig = lane&3)),
// "unit" = half2 covering k = 2u, 2u+1:
//   A frag (16 x k16): elem (row, u): slot = (row&7)*4 + (u&3),
//       reg = (row>=8) + 2*(u>=4).  Stored [frag][psw(slot)+reg], stride 132 u32.
//   B frag (k16 x n8): elem (u, n): slot = (n&7)*4 + (u&3), reg = u>>2.
//       Stored [frag][slot*2+reg], stride 66 u32.
//   C frag: c0=(gid,2tig) c1=(gid,2tig+1) c2,c3 = row+8.

// ---------------------------------------------------------------------------
// FP16 GEMM:  C[M,N] = A[M,K] @ W[N,K]^T + bias[N]
// Block 128x128, BK=32 (2 k16 slices), 256 thr, warp tile 32x64, dbl buffer.
// grid.z selects (W,bias,C) so the three QKV GEMMs fuse into one launch.
// ---------------------------------------------------------------------------
__global__ __launch_bounds__(256, 2) void gemm_fp16(
    const float* __restrict__ A,
    const float* __restrict__ W0, const float* __restrict__ W1, const float* __restrict__ W2,
    const float* __restrict__ b0, const float* __restrict__ b1, const float* __restrict__ b2,
    float* __restrict__ C0, float* __restrict__ C1, float* __restrict__ C2)
{
    __shared__ uint32_t Af[2][16 * 132];   // 16 frags (mtile*2+sl)
    __shared__ uint32_t Bf[2][32 * 66];    // 32 frags (ntile*2+sl)

    const int z = blockIdx.z;
    const float* W    = (z == 0) ? W0 : (z == 1) ? W1 : W2;
    const float* bias = (z == 0) ? b0 : (z == 1) ? b1 : b2;
    float*       C    = (z == 0) ? C0 : (z == 1) ? C1 : C2;

    const int tid  = threadIdx.x;
    const int lane = tid & 31;
    const int warp = tid >> 5;
    const int gid  = lane >> 2;
    const int tig  = lane & 3;
    const int t0   = (warp >> 1) * 2;    // warp's first m16 tile
    const int nb0  = (warp & 1) * 8;     // warp's first n8 tile

    const int block_m = blockIdx.y * 128;
    const int block_n = blockIdx.x * 128;

    const int lrow = tid >> 1;           // 0..127
    const int sl   = tid & 1;            // k16 slice 0/1

    const float* Aptr = A + (size_t)(block_m + lrow) * DMODEL + sl * 16;
    const float* Wptr = W + (size_t)(block_n + lrow) * DMODEL + sl * 16;

    const int a_fr  = ((lrow >> 4) * 2 + sl) * 132;
    const int a_sl0 = (lrow & 7) * 4;
    const int a_rh  = (lrow >> 3) & 1;
    const int b_fr  = ((lrow >> 3) * 2 + sl) * 66;
    const int b_sl0 = (lrow & 7) * 4;
    const int pswl  = psw(lane);

    float acc[2][8][4];
    #pragma unroll
    for (int mt = 0; mt < 2; mt++)
        #pragma unroll
        for (int nt = 0; nt < 8; nt++)
            #pragma unroll
            for (int r = 0; r < 4; r++) acc[mt][nt][r] = 0.f;

    // ---- prologue: stage chunk 0 into buf 0 ----
    {
        uint32_t pa[8], pb[8];
        #pragma unroll
        for (int q = 0; q < 4; q++) {
            float4 a4 = __ldg((const float4*)(Aptr + q * 4));
            float4 w4 = __ldg((const float4*)(Wptr + q * 4));
            pa[q*2+0] = f2h2(a4.x, a4.y); pa[q*2+1] = f2h2(a4.z, a4.w);
            pb[q*2+0] = f2h2(w4.x, w4.y); pb[q*2+1] = f2h2(w4.z, w4.w);
        }
        #pragma unroll
        for (int u = 0; u < 8; u++)
            Af[0][a_fr + psw(a_sl0 + (u & 3)) + a_rh + 2 * (u >> 2)] = pa[u];
        #pragma unroll
        for (int u = 0; u < 4; u++)
            *(uint2*)&Bf[0][b_fr + (b_sl0 + u) * 2] = make_uint2(pb[u], pb[u + 4]);
    }
    __syncthreads();

    const int NK = DMODEL / 32;   // 32
    for (int kt = 0; kt < NK; ++kt) {
        const int cur = kt & 1;
        uint32_t pa[8], pb[8];
        if (kt < NK - 1) {
            const float* ap = Aptr + (kt + 1) * 32;
            const float* wp = Wptr + (kt + 1) * 32;
            #pragma unroll
            for (int q = 0; q < 4; q++) {
                float4 a4 = __ldg((const float4*)(ap + q * 4));
                float4 w4 = __ldg((const float4*)(wp + q * 4));
                pa[q*2+0] = f2h2(a4.x, a4.y); pa[q*2+1] = f2h2(a4.z, a4.w);
                pb[q*2+0] = f2h2(w4.x, w4.y); pb[q*2+1] = f2h2(w4.z, w4.w);
            }
        }

        const uint32_t* AfB = Af[cur];
        const uint32_t* BfB = Bf[cur];
        #pragma unroll
        for (int ks = 0; ks < 2; ++ks) {
            uint4 fa0 = *(const uint4*)&AfB[((t0    ) * 2 + ks) * 132 + pswl];
            uint4 fa1 = *(const uint4*)&AfB[((t0 + 1) * 2 + ks) * 132 + pswl];
            uint2 fb[8];
            #pragma unroll
            for (int nt = 0; nt < 8; nt++)
                fb[nt] = *(const uint2*)&BfB[((nb0 + nt) * 2 + ks) * 66 + lane * 2];
            #pragma unroll
            for (int nt = 0; nt < 8; nt++) {
                mma16(acc[0][nt], (const uint32_t*)&fa0, (const uint32_t*)&fb[nt]);
                mma16(acc[1][nt], (const uint32_t*)&fa1, (const uint32_t*)&fb[nt]);
            }
        }

        if (kt < NK - 1) {
            const int nxt = cur ^ 1;
            #pragma unroll
            for (int u = 0; u < 8; u++)
                Af[nxt][a_fr + psw(a_sl0 + (u & 3)) + a_rh + 2 * (u >> 2)] = pa[u];
            #pragma unroll
            for (int u = 0; u < 4; u++)
                *(uint2*)&Bf[nxt][b_fr + (b_sl0 + u) * 2] = make_uint2(pb[u], pb[u + 4]);
        }
        __syncthreads();
    }

    // ---- epilogue with bias ----
    const int m0  = (warp >> 1) * 32;
    const int n0w = (warp & 1) * 64;
    #pragma unroll
    for (int mt = 0; mt < 2; mt++) {
        #pragma unroll
        for (int nt = 0; nt < 8; nt++) {
            const int row = block_m + m0 + mt * 16 + gid;
            const int col = block_n + n0w + nt * 8 + tig * 2;
            const float bx = bias[col], by = bias[col + 1];
            float2 v0 = { acc[mt][nt][0] + bx, acc[mt][nt][1] + by };
            float2 v1 = { acc[mt][nt][2] + bx, acc[mt][nt][3] + by };
            *(float2*)(C + (size_t)row * DMODEL + col)       = v0;
            *(float2*)(C + (size_t)(row + 8) * DMODEL + col) = v1;
        }
    }
}

// ---------------------------------------------------------------------------
// Flash attention, FP16 MMA, packed-fragment smem.
// Block 256 thr = 8 warps; warp owns 16 q rows. 128-key tiles, two 64-key
// sub-rounds. exp2-domain softmax (log2e folded into Q scale).
// Qf (A-frags of Q) aliases Pf (A-frags of P) — Q lives in regs after load.
// ---------------------------------------------------------------------------
#define ATT_QF_U32  (32 * 132)     // 4224: 8 rowgroups x 4 slices
#define ATT_KF_U32  (64 * 66)      // 4224: 16 keygroups x 4 slices
#define ATT_VF_U32  (64 * 66)      // 4224: 2 halves x (4 slices x 8 ntiles)
#define ATT_SMEM_U32 (ATT_QF_U32 + ATT_KF_U32 + ATT_VF_U32)
#define ATT_SMEM_BYTES (ATT_SMEM_U32 * 4)   // 50688

__global__ __launch_bounds__(256, 2) void attn_mma(
    const float* __restrict__ Qp, const float* __restrict__ Kp,
    const float* __restrict__ Vp, float* __restrict__ Ctx)
{
    extern __shared__ uint32_t sm[];
    uint32_t* QfPf = sm;                        // Q A-frags, later P A-frags
    uint32_t* Kf   = sm + ATT_QF_U32;
    uint32_t* Vf   = sm + ATT_QF_U32 + ATT_KF_U32;

    const int tid  = threadIdx.x;
    const int lane = tid & 31;
    const int warp = tid >> 5;
    const int gid  = lane >> 2;
    const int tig  = lane & 3;
    const int q0   = warp * 16;
    const int pswl = psw(lane);

    const int b     = blockIdx.z;
    const int h     = blockIdx.y;
    const int q_blk = blockIdx.x * 128;

    // scale: 1/sqrt(64) * log2(e)  (exp2-domain softmax)
    const float sc = 0.125f * 1.4426950408889634f;

    // ---- stage Q into A-fragment layout ----
    const float* qbase = Qp + ((size_t)(b * SEQ + q_blk)) * DMODEL + h * DHEAD;
    #pragma unroll
    for (int r = 0; r < 8; r++) {
        int li  = r * 256 + tid;
        int row = li >> 4;
        int f4  = (li & 15) * 4;
        float4 v = *(const float4*)(qbase + (size_t)row * DMODEL + f4);
        const int slice = f4 >> 4;
        const int uu    = (f4 >> 1) & 7;
        const int frag  = ((row >> 4) * 4 + slice) * 132;
        const int rb    = (row >> 3) & 1;
        QfPf[frag + psw((row & 7) * 4 + (uu & 3))       + rb + 2 * (uu >> 2)]
            = f2h2(v.x * sc, v.y * sc);
        QfPf[frag + psw((row & 7) * 4 + ((uu + 1) & 3)) + rb + 2 * ((uu + 1) >> 2)]
            = f2h2(v.z * sc, v.w * sc);
    }
    __syncthreads();

    uint4 aq[4];
    #pragma unroll
    for (int ks = 0; ks < 4; ks++)
        aq[ks] = *(const uint4*)&QfPf[(warp * 4 + ks) * 132 + pswl];

    float o[8][4];
    #pragma unroll
    for (int dt = 0; dt < 8; dt++)
        #pragma unroll
        for (int r = 0; r < 4; r++) o[dt][r] = 0.f;
    float m0 = -1e30f, m1 = -1e30f, l0 = 0.f, l1 = 0.f;

    const float* kbase = Kp + ((size_t)b * SEQ) * DMODEL + h * DHEAD;
    const float* vbase = Vp + ((size_t)b * SEQ) * DMODEL + h * DHEAD;

    uint32_t* PfW = QfPf + warp * (4 * 132);

    for (int kt = 0; kt < SEQ / 128; ++kt) {
        __syncthreads();   // prior tile fully consumed (aq regs hold Q; Pf reuse safe)

        // ---- stage 128 keys x 64 dh ----
        #pragma unroll
        for (int r = 0; r < 8; r++) {
            int li  = r * 256 + tid;
            int key = li >> 4;            // 0..127
            int f4  = (li & 15) * 4;
            const size_t off = (size_t)(kt * 128 + key) * DMODEL + f4;
            float4 kv = *(const float4*)(kbase + off);
            float4 vv = *(const float4*)(vbase + off);

            {   // K as B-frag (k=dh): frag = (key>>3)*4 + slice
                const int slice = f4 >> 4;
                const int uu    = (f4 >> 1) & 7;
                uint32_t* dk = Kf + ((key >> 3) * 4 + slice) * 66;
                dk[((key & 7) * 4 + (uu & 3)) * 2 + (uu >> 2)]             = f2h2(kv.x, kv.y);
                dk[((key & 7) * 4 + ((uu + 1) & 3)) * 2 + ((uu + 1) >> 2)] = f2h2(kv.z, kv.w);
            }
            {   // V as B-frag (k=key): half2 packs key pairs -> lane-xor-16 exchange
                float px = __shfl_xor_sync(0xffffffffu, vv.x, 16);
                float py = __shfl_xor_sync(0xffffffffu, vv.y, 16);
                float pz = __shfl_xor_sync(0xffffffffu, vv.z, 16);
                float pw = __shfl_xor_sync(0xffffffffu, vv.w, 16);
                if ((tid & 16) == 0) {      // even key holds (key, key+1)
                    const int kk    = key & 63;
                    const int hf    = key >> 6;
                    const int slice = kk >> 4;
                    const int u     = (kk >> 1) & 7;
                    uint32_t* dv = Vf + hf * 2112
                                 + (slice * 8 + (f4 >> 3)) * 66 + (u >> 2);
                    const int s0 = (f4 & 7) * 4 + (u & 3);
                    dv[(s0     ) * 2] = f2h2(vv.x, px);
                    dv[(s0 +  4) * 2] = f2h2(vv.y, py);
                    dv[(s0 +  8) * 2] = f2h2(vv.z, pz);
                    dv[(s0 + 12) * 2] = f2h2(vv.w, pw);
                }
            }
        }
        __syncthreads();

        // ---- two 64-key sub-rounds ----
        #pragma unroll
        for (int hf = 0; hf < 2; ++hf) {
            const uint32_t* KfH = Kf + hf * 2112;
            const uint32_t* VfH = Vf + hf * 2112;

            float s[8][4];
            #pragma unroll
            for (int nt = 0; nt < 8; nt++)
                #pragma unroll
                for (int r = 0; r < 4; r++) s[nt][r] = 0.f;

            #pragma unroll
            for (int ks = 0; ks < 4; ks++) {
                uint2 kb[8];
                #pragma unroll
                for (int nt = 0; nt < 8; nt++)
                    kb[nt] = *(const uint2*)&KfH[(nt * 4 + ks) * 66 + lane * 2];
                #pragma unroll
                for (int nt = 0; nt < 8; nt++)
                    mma16(s[nt], (const uint32_t*)&aq[ks], (const uint32_t*)&kb[nt]);
            }

            // online softmax (exp2 domain)
            float mx0 = -1e30f, mx1 = -1e30f;
            #pragma unroll
            for (int nt = 0; nt < 8; nt++) {
                mx0 = fmaxf(mx0, fmaxf(s[nt][0], s[nt][1]));
                mx1 = fmaxf(mx1, fmaxf(s[nt][2], s[nt][3]));
            }
            mx0 = fmaxf(mx0, __shfl_xor_sync(0xffffffffu, mx0, 1));
            mx0 = fmaxf(mx0, __shfl_xor_sync(0xffffffffu, mx0, 2));
            mx1 = fmaxf(mx1, __shfl_xor_sync(0xffffffffu, mx1, 1));
            mx1 = fmaxf(mx1, __shfl_xor_sync(0xffffffffu, mx1, 2));

            const float nm0 = fmaxf(m0, mx0), nm1 = fmaxf(m1, mx1);
            const float c0 = ex2f(m0 - nm0), c1 = ex2f(m1 - nm1);
            m0 = nm0; m1 = nm1;

            float ls0 = 0.f, ls1 = 0.f;
            #pragma unroll
            for (int nt = 0; nt < 8; nt++) {
                s[nt][0] = ex2f(s[nt][0] - m0);
                s[nt][1] = ex2f(s[nt][1] - m0);
                s[nt][2] = ex2f(s[nt][2] - m1);
                s[nt][3] = ex2f(s[nt][3] - m1);
                ls0 += s[nt][0] + s[nt][1];
                ls1 += s[nt][2] + s[nt][3];
            }
            l0 = l0 * c0 + ls0;
            l1 = l1 * c1 + ls1;
            #pragma unroll
            for (int dt = 0; dt < 8; dt++) {
                o[dt][0] *= c0; o[dt][1] *= c0;
                o[dt][2] *= c1; o[dt][3] *= c1;
            }

            // P accumulator -> A-fragment smem (per-warp slice, STS.64)
            #pragma unroll
            for (int nt = 0; nt < 8; nt++) {
                uint32_t hlo = f2h2(s[nt][0], s[nt][1]);   // row gid
                uint32_t hhi = f2h2(s[nt][2], s[nt][3]);   // row gid+8
                *(uint2*)&PfW[(nt >> 1) * 132 + pswl + (nt & 1) * 2]
                    = make_uint2(hlo, hhi);
            }
            __syncwarp();

            // O += P V
            #pragma unroll
            for (int ks = 0; ks < 4; ks++) {
                uint4 ap = *(const uint4*)&PfW[ks * 132 + pswl];
                #pragma unroll
                for (int nt = 0; nt < 8; nt++) {
                    uint2 vb = *(const uint2*)&VfH[(ks * 8 + nt) * 66 + lane * 2];
                    mma16(o[nt], (const uint32_t*)&ap, (const uint32_t*)&vb);
                }
            }
            __syncwarp();
        }
    }

    // ---- finalize ----
    l0 += __shfl_xor_sync(0xffffffffu, l0, 1);
    l0 += __shfl_xor_sync(0xffffffffu, l0, 2);
    l1 += __shfl_xor_sync(0xffffffffu, l1, 1);
    l1 += __shfl_xor_sync(0xffffffffu, l1, 2);
    const float i0 = 1.f / l0, i1 = 1.f / l1;

    float* cp0 = Ctx + ((size_t)(b * SEQ + q_blk + q0 + gid)) * DMODEL + h * DHEAD;
    float* cp1 = cp0 + (size_t)8 * DMODEL;
    #pragma unroll
    for (int nt = 0; nt < 8; nt++) {
        const int col = nt * 8 + tig * 2;
        float2 v0 = { o[nt][0] * i0, o[nt][1] * i0 };
        float2 v1 = { o[nt][2] * i1, o[nt][3] * i1 };
        *(float2*)(cp0 + col) = v0;
        *(float2*)(cp1 + col) = v1;
    }
}

// ---------------------------------------------------------------------------
extern "C" void kernel_launch(void* const* d_in, const int* in_sizes, int n_in,
                              void* d_out, int out_size)
{
    const float* x  = (const float*)d_in[0];
    const float* Wq = (const float*)d_in[1];
    const float* bq = (const float*)d_in[2];
    const float* Wk = (const float*)d_in[3];
    const float* bk = (const float*)d_in[4];
    const float* Wv = (const float*)d_in[5];
    const float* bv = (const float*)d_in[6];
    const float* Wo = (const float*)d_in[7];
    const float* bo = (const float*)d_in[8];
    float* out = (float*)d_out;

    float *Qd, *Kd, *Vd, *Cd;
    cudaGetSymbolAddress((void**)&Qd, g_Q);
    cudaGetSymbolAddress((void**)&Kd, g_K);
    cudaGetSymbolAddress((void**)&Vd, g_V);
    cudaGetSymbolAddress((void**)&Cd, g_C);

    static bool attr_set = false;
    if (!attr_set) {
        cudaFuncSetAttribute(attn_mma,
                             cudaFuncAttributeMaxDynamicSharedMemorySize,
                             ATT_SMEM_BYTES);
        attr_set = true;
    }

    dim3 gqkv(DMODEL / 128, MTOT / 128, 3);   // (8, 32, 3): Q,K,V in one launch
    gemm_fp16<<<gqkv, 256>>>(x, Wq, Wk, Wv, bq, bk, bv, Qd, Kd, Vd);

    dim3 agrid(SEQ / 128, HEADS, BATCH);      // (16, 16, 2)
    attn_mma<<<agrid, 256, ATT_SMEM_BYTES>>>(Qd, Kd, Vd, Cd);

    dim3 gout(DMODEL / 128, MTOT / 128, 1);
    gemm_fp16<<<gout, 256>>>(Cd, Wo, Wo, Wo, bo, bo, bo, out, out, out);
}

// round 9
// speedup vs baseline: 9.0884x; 1.5819x over previous
#include <cuda_runtime.h>
#include <cuda_fp16.h>
#include <cstdint>

#define BATCH   2
#define SEQ     2048
#define DMODEL  1024
#define HEADS   16
#define DHEAD   64
#define MTOT    (BATCH * SEQ)   // 4096

// fp16 intermediates (allocation-free rule: __device__ globals)
__device__ __half g_Xh [MTOT * DMODEL];
__device__ __half g_Wqh[DMODEL * DMODEL];
__device__ __half g_Wkh[DMODEL * DMODEL];
__device__ __half g_Wvh[DMODEL * DMODEL];
__device__ __half g_Woh[DMODEL * DMODEL];
__device__ __half g_Qh [MTOT * DMODEL];
__device__ __half g_Kh [MTOT * DMODEL];
__device__ __half g_Vh [MTOT * DMODEL];
__device__ __half g_Ch [MTOT * DMODEL];

// ---------------------------------------------------------------------------
// helpers
// ---------------------------------------------------------------------------
__device__ __forceinline__ uint32_t f2h2(float lo, float hi) {
    __half2 h = __floats2half2_rn(lo, hi);
    return *(uint32_t*)&h;
}
__device__ __forceinline__ float ex2f(float x) {
    float y;
    asm("ex2.approx.ftz.f32 %0, %1;" : "=f"(y) : "f"(x));
    return y;
}
__device__ __forceinline__ uint32_t smem_u32(const void* p) {
    uint32_t a;
    asm("{ .reg .u64 t; cvta.to.shared.u64 t, %1; cvt.u32.u64 %0, t; }"
        : "=r"(a) : "l"(p));
    return a;
}
__device__ __forceinline__ int psw(int s) {            // attention A-frag swizzle
    return (s * 4) ^ (((s >> 3) & 3) << 2);
}
__device__ __forceinline__ void mma16(float* d, const uint32_t* a, const uint32_t* b) {
    asm volatile(
        "mma.sync.aligned.m16n8k16.row.col.f32.f16.f16.f32 "
        "{%0,%1,%2,%3}, {%4,%5,%6,%7}, {%8,%9}, {%0,%1,%2,%3};\n"
        : "+f"(d[0]), "+f"(d[1]), "+f"(d[2]), "+f"(d[3])
        : "r"(a[0]), "r"(a[1]), "r"(a[2]), "r"(a[3]), "r"(b[0]), "r"(b[1]));
}
__device__ __forceinline__ void cp16(uint32_t sm, const void* gm) {
    asm volatile("cp.async.cg.shared.global [%0], [%1], 16;" :: "r"(sm), "l"(gm));
}
__device__ __forceinline__ void cp_commit() {
    asm volatile("cp.async.commit_group;" ::: "memory");
}
template<int N> __device__ __forceinline__ void cp_wait() {
    asm volatile("cp.async.wait_group %0;" :: "n"(N) : "memory");
}
__device__ __forceinline__ void ldsm4(uint32_t* r, uint32_t addr) {
    asm volatile("ldmatrix.sync.aligned.m8n8.x4.shared.b16 {%0,%1,%2,%3}, [%4];"
        : "=r"(r[0]), "=r"(r[1]), "=r"(r[2]), "=r"(r[3]) : "r"(addr));
}

// ---------------------------------------------------------------------------
// fp32 -> fp16 convert (one-time pass)
// ---------------------------------------------------------------------------
__global__ void f2h_kernel(const float4* __restrict__ src, uint2* __restrict__ dst, int n4)
{
    int i = blockIdx.x * blockDim.x + threadIdx.x;
    if (i < n4) {
        float4 v = src[i];
        dst[i] = make_uint2(f2h2(v.x, v.y), f2h2(v.z, v.w));
    }
}

// ---------------------------------------------------------------------------
// FP16 GEMM via cp.async + ldmatrix:  C[M,N] = A[M,K] @ W[N,K]^T + bias[N]
// CTA 128x128, 4 warps of 64x64, BK=32, 3-stage pipeline.
// smem tile: row-major 128 rows x 64B (32 halves), 16B-unit swizzle:
//   off(row,c16) = row*64 + ((c16 ^ ((row>>1)&3)) << 4)
// ---------------------------------------------------------------------------
#define G_STAGE_BYTES 16384                 // A 8K + B 8K
#define G_SMEM_BYTES  (3 * G_STAGE_BYTES)   // 49152

template<bool OUT_HALF>
__global__ __launch_bounds__(128, 2) void gemm_ldsm(
    const __half* __restrict__ A,
    const __half* __restrict__ W0, const __half* __restrict__ W1, const __half* __restrict__ W2,
    const float* __restrict__ b0, const float* __restrict__ b1, const float* __restrict__ b2,
    void* __restrict__ C0, void* __restrict__ C1, void* __restrict__ C2)
{
    extern __shared__ char gsm[];
    const int z = blockIdx.z;
    const __half* W    = (z == 0) ? W0 : (z == 1) ? W1 : W2;
    const float*  bias = (z == 0) ? b0 : (z == 1) ? b1 : b2;
    void*         Cv   = (z == 0) ? C0 : (z == 1) ? C1 : C2;

    const int tid  = threadIdx.x;
    const int lane = tid & 31;
    const int warp = tid >> 5;
    const int mw   = (warp >> 1) * 64;
    const int nw   = (warp & 1) * 64;
    const int block_m = blockIdx.y * 128;
    const int block_n = blockIdx.x * 128;
    const uint32_t smb = smem_u32(gsm);

    // producer coords: idx -> (row, c16)
    const int p_row = tid >> 2;         // rows 0..31 (+32*i)
    const int p_c16 = tid & 3;

    float acc[4][8][4];
    #pragma unroll
    for (int mt = 0; mt < 4; mt++)
        #pragma unroll
        for (int nt = 0; nt < 8; nt++)
            #pragma unroll
            for (int r = 0; r < 4; r++) acc[mt][nt][r] = 0.f;

    // ---- stage copy ----
    auto stage_copy = [&](int st, int kt) {
        const uint32_t sA = smb + st * G_STAGE_BYTES;
        const uint32_t sB = sA + 8192;
        #pragma unroll
        for (int i = 0; i < 4; i++) {
            const int row = p_row + i * 32;
            const uint32_t so = row * 64 + ((p_c16 ^ ((row >> 1) & 3)) << 4);
            cp16(sA + so, A + (size_t)(block_m + row) * DMODEL + kt * 32 + p_c16 * 8);
            cp16(sB + so, W + (size_t)(block_n + row) * DMODEL + kt * 32 + p_c16 * 8);
        }
    };

    stage_copy(0, 0); cp_commit();
    stage_copy(1, 1); cp_commit();

    const int NK = DMODEL / 32;   // 32
    const int mat  = lane >> 3;
    const int lrow = lane & 7;
    int st = 0;

    for (int kt = 0; kt < NK; ++kt) {
        cp_wait<1>();
        __syncthreads();
        if (kt + 2 < NK) stage_copy((st + 2) % 3, kt + 2);
        cp_commit();

        const uint32_t sA = smb + st * G_STAGE_BYTES;
        const uint32_t sB = sA + 8192;

        #pragma unroll
        for (int ks = 0; ks < 2; ++ks) {
            uint32_t a[4][4];
            #pragma unroll
            for (int mt = 0; mt < 4; mt++) {
                const int row = mw + mt * 16 + (mat & 1) * 8 + lrow;
                const int c16 = ks * 2 + (mat >> 1);
                ldsm4(a[mt], sA + row * 64 + ((c16 ^ ((row >> 1) & 3)) << 4));
            }
            uint32_t bb[4][4];
            #pragma unroll
            for (int np = 0; np < 4; np++) {
                const int row = nw + np * 16 + (mat >> 1) * 8 + lrow;
                const int c16 = ks * 2 + (mat & 1);
                ldsm4(bb[np], sB + row * 64 + ((c16 ^ ((row >> 1) & 3)) << 4));
            }
            #pragma unroll
            for (int mt = 0; mt < 4; mt++)
                #pragma unroll
                for (int np = 0; np < 4; np++) {
                    mma16(acc[mt][np * 2],     a[mt], &bb[np][0]);
                    mma16(acc[mt][np * 2 + 1], a[mt], &bb[np][2]);
                }
        }
        __syncthreads();
        st = (st + 1) % 3;
    }

    // ---- epilogue with bias ----
    const int gid = lane >> 2, tig = lane & 3;
    #pragma unroll
    for (int mt = 0; mt < 4; mt++) {
        const int row = block_m + mw + mt * 16 + gid;
        #pragma unroll
        for (int nt = 0; nt < 8; nt++) {
            const int col = block_n + nw + nt * 8 + tig * 2;
            const float bx = __ldg(bias + col), by = __ldg(bias + col + 1);
            const float v00 = acc[mt][nt][0] + bx, v01 = acc[mt][nt][1] + by;
            const float v10 = acc[mt][nt][2] + bx, v11 = acc[mt][nt][3] + by;
            if (OUT_HALF) {
                __half* C = (__half*)Cv;
                *(uint32_t*)(C + (size_t)row * DMODEL + col)       = f2h2(v00, v01);
                *(uint32_t*)(C + (size_t)(row + 8) * DMODEL + col) = f2h2(v10, v11);
            } else {
                float* C = (float*)Cv;
                *(float2*)(C + (size_t)row * DMODEL + col)       = make_float2(v00, v01);
                *(float2*)(C + (size_t)(row + 8) * DMODEL + col) = make_float2(v10, v11);
            }
        }
    }
}

// ---------------------------------------------------------------------------
// Flash attention, FP16 MMA, packed-fragment smem, fp16 I/O.
// Block 256 thr = 8 warps; warp owns 16 q rows. 128-key tiles, two 64-key
// sub-rounds. exp2-domain softmax.
// ---------------------------------------------------------------------------
#define ATT_QF_U32  (32 * 132)
#define ATT_KF_U32  (64 * 66)
#define ATT_VF_U32  (64 * 66)
#define ATT_SMEM_U32 (ATT_QF_U32 + ATT_KF_U32 + ATT_VF_U32)
#define ATT_SMEM_BYTES (ATT_SMEM_U32 * 4)   // 50688

__global__ __launch_bounds__(256, 2) void attn_mma(
    const __half* __restrict__ Qp, const __half* __restrict__ Kp,
    const __half* __restrict__ Vp, __half* __restrict__ Ctx)
{
    extern __shared__ uint32_t sm[];
    uint32_t* QfPf = sm;
    uint32_t* Kf   = sm + ATT_QF_U32;
    uint32_t* Vf   = sm + ATT_QF_U32 + ATT_KF_U32;

    const int tid  = threadIdx.x;
    const int lane = tid & 31;
    const int warp = tid >> 5;
    const int gid  = lane >> 2;
    const int tig  = lane & 3;
    const int q0   = warp * 16;
    const int pswl = psw(lane);

    const int b     = blockIdx.z;
    const int h     = blockIdx.y;
    const int q_blk = blockIdx.x * 128;

    const float sc = 0.125f * 1.4426950408889634f;   // 1/sqrt(64) * log2(e)

    // ---- stage Q into A-fragment layout (scale in fp32) ----
    const __half* qbase = Qp + (size_t)(b * SEQ + q_blk) * DMODEL + h * DHEAD;
    #pragma unroll
    for (int r = 0; r < 4; r++) {
        const int li  = r * 256 + tid;
        const int row = li >> 3;
        const int g8  = li & 7;
        uint4 qv = *(const uint4*)(qbase + (size_t)row * DMODEL + g8 * 8);
        uint32_t u[4] = { qv.x, qv.y, qv.z, qv.w };
        #pragma unroll
        for (int j = 0; j < 4; j++) {
            float2 f = __half22float2(*(__half2*)&u[j]);
            u[j] = f2h2(f.x * sc, f.y * sc);
        }
        const int slice = g8 >> 1;
        const int lu0   = (g8 & 1) * 4;
        const int frag  = ((row >> 4) * 4 + slice) * 132;
        const int rb    = (row >> 3) & 1;
        #pragma unroll
        for (int j = 0; j < 4; j++) {
            const int lu = lu0 + j;
            QfPf[frag + psw((row & 7) * 4 + (lu & 3)) + rb + 2 * (lu >> 2)] = u[j];
        }
    }
    __syncthreads();

    uint4 aq[4];
    #pragma unroll
    for (int ks = 0; ks < 4; ks++)
        aq[ks] = *(const uint4*)&QfPf[(warp * 4 + ks) * 132 + pswl];

    float o[8][4];
    #pragma unroll
    for (int dt = 0; dt < 8; dt++)
        #pragma unroll
        for (int r = 0; r < 4; r++) o[dt][r] = 0.f;
    float m0 = -1e30f, m1 = -1e30f, l0 = 0.f, l1 = 0.f;

    const __half* kbase = Kp + (size_t)(b * SEQ) * DMODEL + h * DHEAD;
    const __half* vbase = Vp + (size_t)(b * SEQ) * DMODEL + h * DHEAD;

    uint32_t* PfW = QfPf + warp * (4 * 132);

    for (int kt = 0; kt < SEQ / 128; ++kt) {
        __syncthreads();

        // ---- stage 128 keys x 64 dh (fp16 loads) ----
        #pragma unroll
        for (int r = 0; r < 4; r++) {
            const int li  = r * 256 + tid;
            const int key = li >> 3;
            const int g8  = li & 7;
            const size_t off = (size_t)(kt * 128 + key) * DMODEL + g8 * 8;
            uint4 kv = *(const uint4*)(kbase + off);
            uint4 vv = *(const uint4*)(vbase + off);

            const int slice = g8 >> 1;
            const int lu0   = (g8 & 1) * 4;

            {   // K as B-frag (k = dh)
                uint32_t* dk = Kf + ((key >> 3) * 4 + slice) * 66;
                const uint32_t uk[4] = { kv.x, kv.y, kv.z, kv.w };
                #pragma unroll
                for (int j = 0; j < 4; j++) {
                    const int lu = lu0 + j;
                    dk[((key & 7) * 4 + (lu & 3)) * 2 + (lu >> 2)] = uk[j];
                }
            }
            {   // V as B-frag (k = key): pair adjacent keys via lane-xor-8
                uint32_t uv[4] = { vv.x, vv.y, vv.z, vv.w };
                uint32_t pv[4];
                #pragma unroll
                for (int j = 0; j < 4; j++)
                    pv[j] = __shfl_xor_sync(0xffffffffu, uv[j], 8);
                if ((key & 1) == 0) {
                    const int kk = key & 63;
                    const int hf = key >> 6;
                    const int uK = (kk >> 1) & 7;
                    uint32_t* dv = Vf + hf * 2112 + ((kk >> 4) * 8 + g8) * 66;
                    #pragma unroll
                    for (int j = 0; j < 4; j++) {
                        __half2 mine = *(__half2*)&uv[j];
                        __half2 peer = *(__half2*)&pv[j];
                        __half2 lo = __lows2half2(mine, peer);   // n = g8*8 + 2j
                        __half2 hi = __highs2half2(mine, peer);  // n = g8*8 + 2j+1
                        dv[((2 * j    ) * 4 + (uK & 3)) * 2 + (uK >> 2)] = *(uint32_t*)&lo;
                        dv[((2 * j + 1) * 4 + (uK & 3)) * 2 + (uK >> 2)] = *(uint32_t*)&hi;
                    }
                }
            }
        }
        __syncthreads();

        // ---- two 64-key sub-rounds ----
        #pragma unroll
        for (int hf = 0; hf < 2; ++hf) {
            const uint32_t* KfH = Kf + hf * 2112;
            const uint32_t* VfH = Vf + hf * 2112;

            float s[8][4];
            #pragma unroll
            for (int nt = 0; nt < 8; nt++)
                #pragma unroll
                for (int r = 0; r < 4; r++) s[nt][r] = 0.f;

            #pragma unroll
            for (int ks = 0; ks < 4; ks++) {
                uint2 kb[8];
                #pragma unroll
                for (int nt = 0; nt < 8; nt++)
                    kb[nt] = *(const uint2*)&KfH[(nt * 4 + ks) * 66 + lane * 2];
                #pragma unroll
                for (int nt = 0; nt < 8; nt++)
                    mma16(s[nt], (const uint32_t*)&aq[ks], (const uint32_t*)&kb[nt]);
            }

            float mx0 = -1e30f, mx1 = -1e30f;
            #pragma unroll
            for (int nt = 0; nt < 8; nt++) {
                mx0 = fmaxf(mx0, fmaxf(s[nt][0], s[nt][1]));
                mx1 = fmaxf(mx1, fmaxf(s[nt][2], s[nt][3]));
            }
            mx0 = fmaxf(mx0, __shfl_xor_sync(0xffffffffu, mx0, 1));
            mx0 = fmaxf(mx0, __shfl_xor_sync(0xffffffffu, mx0, 2));
            mx1 = fmaxf(mx1, __shfl_xor_sync(0xffffffffu, mx1, 1));
            mx1 = fmaxf(mx1, __shfl_xor_sync(0xffffffffu, mx1, 2));

            const float nm0 = fmaxf(m0, mx0), nm1 = fmaxf(m1, mx1);
            const float c0 = ex2f(m0 - nm0), c1 = ex2f(m1 - nm1);
            m0 = nm0; m1 = nm1;

            float ls0 = 0.f, ls1 = 0.f;
            #pragma unroll
            for (int nt = 0; nt < 8; nt++) {
                s[nt][0] = ex2f(s[nt][0] - m0);
                s[nt][1] = ex2f(s[nt][1] - m0);
                s[nt][2] = ex2f(s[nt][2] - m1);
                s[nt][3] = ex2f(s[nt][3] - m1);
                ls0 += s[nt][0] + s[nt][1];
                ls1 += s[nt][2] + s[nt][3];
            }
            l0 = l0 * c0 + ls0;
            l1 = l1 * c1 + ls1;
            #pragma unroll
            for (int dt = 0; dt < 8; dt++) {
                o[dt][0] *= c0; o[dt][1] *= c0;
                o[dt][2] *= c1; o[dt][3] *= c1;
            }

            #pragma unroll
            for (int nt = 0; nt < 8; nt++) {
                uint32_t hlo = f2h2(s[nt][0], s[nt][1]);
                uint32_t hhi = f2h2(s[nt][2], s[nt][3]);
                *(uint2*)&PfW[(nt >> 1) * 132 + pswl + (nt & 1) * 2]
                    = make_uint2(hlo, hhi);
            }
            __syncwarp();

            #pragma unroll
            for (int ks = 0; ks < 4; ks++) {
                uint4 ap = *(const uint4*)&PfW[ks * 132 + pswl];
                #pragma unroll
                for (int nt = 0; nt < 8; nt++) {
                    uint2 vb = *(const uint2*)&VfH[(ks * 8 + nt) * 66 + lane * 2];
                    mma16(o[nt], (const uint32_t*)&ap, (const uint32_t*)&vb);
                }
            }
            __syncwarp();
        }
    }

    // ---- finalize (fp16 out) ----
    l0 += __shfl_xor_sync(0xffffffffu, l0, 1);
    l0 += __shfl_xor_sync(0xffffffffu, l0, 2);
    l1 += __shfl_xor_sync(0xffffffffu, l1, 1);
    l1 += __shfl_xor_sync(0xffffffffu, l1, 2);
    const float i0 = 1.f / l0, i1 = 1.f / l1;

    __half* cp0 = Ctx + (size_t)(b * SEQ + q_blk + q0 + gid) * DMODEL + h * DHEAD;
    __half* cp1 = cp0 + (size_t)8 * DMODEL;
    #pragma unroll
    for (int nt = 0; nt < 8; nt++) {
        const int col = nt * 8 + tig * 2;
        *(uint32_t*)(cp0 + col) = f2h2(o[nt][0] * i0, o[nt][1] * i0);
        *(uint32_t*)(cp1 + col) = f2h2(o[nt][2] * i1, o[nt][3] * i1);
    }
}

// ---------------------------------------------------------------------------
extern "C" void kernel_launch(void* const* d_in, const int* in_sizes, int n_in,
                              void* d_out, int out_size)
{
    const float* x  = (const float*)d_in[0];
    const float* Wq = (const float*)d_in[1];
    const float* bq = (const float*)d_in[2];
    const float* Wk = (const float*)d_in[3];
    const float* bk = (const float*)d_in[4];
    const float* Wv = (const float*)d_in[5];
    const float* bv = (const float*)d_in[6];
    const float* Wo = (const float*)d_in[7];
    const float* bo = (const float*)d_in[8];
    float* out = (float*)d_out;

    __half *Xh, *Wqh, *Wkh, *Wvh, *Woh, *Qh, *Kh, *Vh, *Ch;
    cudaGetSymbolAddress((void**)&Xh,  g_Xh);
    cudaGetSymbolAddress((void**)&Wqh, g_Wqh);
    cudaGetSymbolAddress((void**)&Wkh, g_Wkh);
    cudaGetSymbolAddress((void**)&Wvh, g_Wvh);
    cudaGetSymbolAddress((void**)&Woh, g_Woh);
    cudaGetSymbolAddress((void**)&Qh,  g_Qh);
    cudaGetSymbolAddress((void**)&Kh,  g_Kh);
    cudaGetSymbolAddress((void**)&Vh,  g_Vh);
    cudaGetSymbolAddress((void**)&Ch,  g_Ch);

    static bool attr_set = false;
    if (!attr_set) {
        cudaFuncSetAttribute(attn_mma,
                             cudaFuncAttributeMaxDynamicSharedMemorySize,
                             ATT_SMEM_BYTES);
        cudaFuncSetAttribute(gemm_ldsm<true>,
                             cudaFuncAttributeMaxDynamicSharedMemorySize,
                             G_SMEM_BYTES);
        cudaFuncSetAttribute(gemm_ldsm<false>,
                             cudaFuncAttributeMaxDynamicSharedMemorySize,
                             G_SMEM_BYTES);
        attr_set = true;
    }

    // ---- 1. fp32 -> fp16 converts ----
    const int xN4 = MTOT * DMODEL / 4;       // 1M
    const int wN4 = DMODEL * DMODEL / 4;     // 256K
    f2h_kernel<<<(xN4 + 255) / 256, 256>>>((const float4*)x,  (uint2*)Xh,  xN4);
    f2h_kernel<<<(wN4 + 255) / 256, 256>>>((const float4*)Wq, (uint2*)Wqh, wN4);
    f2h_kernel<<<(wN4 + 255) / 256, 256>>>((const float4*)Wk, (uint2*)Wkh, wN4);
    f2h_kernel<<<(wN4 + 255) / 256, 256>>>((const float4*)Wv, (uint2*)Wvh, wN4);
    f2h_kernel<<<(wN4 + 255) / 256, 256>>>((const float4*)Wo, (uint2*)Woh, wN4);

    // ---- 2. QKV projections (fused, fp16 out) ----
    dim3 gqkv(DMODEL / 128, MTOT / 128, 3);
    gemm_ldsm<true><<<gqkv, 128, G_SMEM_BYTES>>>(
        Xh, Wqh, Wkh, Wvh, bq, bk, bv, Qh, Kh, Vh);

    // ---- 3. attention ----
    dim3 agrid(SEQ / 128, HEADS, BATCH);
    attn_mma<<<agrid, 256, ATT_SMEM_BYTES>>>(Qh, Kh, Vh, Ch);

    // ---- 4. output projection (fp32 out) ----
    dim3 gout(DMODEL / 128, MTOT / 128, 1);
    gemm_ldsm<false><<<gout, 128, G_SMEM_BYTES>>>(
        Ch, Woh, Woh, Woh, bo, bo, bo, out, out, out);
}

// round 10
// speedup vs baseline: 10.6718x; 1.1742x over previous
#include <cuda_runtime.h>
#include <cuda_fp16.h>
#include <cstdint>

#define BATCH   2
#define SEQ     2048
#define DMODEL  1024
#define HEADS   16
#define DHEAD   64
#define MTOT    (BATCH * SEQ)   // 4096

// fp16 intermediates (allocation-free rule: __device__ globals)
__device__ __half g_Xh [MTOT * DMODEL];
__device__ __half g_Wqh[DMODEL * DMODEL];
__device__ __half g_Wkh[DMODEL * DMODEL];
__device__ __half g_Wvh[DMODEL * DMODEL];
__device__ __half g_Woh[DMODEL * DMODEL];
__device__ __half g_Qh [MTOT * DMODEL];
__device__ __half g_Kh [MTOT * DMODEL];
__device__ __half g_Vh [MTOT * DMODEL];
__device__ __half g_Ch [MTOT * DMODEL];

// ---------------------------------------------------------------------------
// helpers
// ---------------------------------------------------------------------------
__device__ __forceinline__ uint32_t f2h2(float lo, float hi) {
    __half2 h = __floats2half2_rn(lo, hi);
    return *(uint32_t*)&h;
}
__device__ __forceinline__ float ex2f(float x) {
    float y;
    asm("ex2.approx.ftz.f32 %0, %1;" : "=f"(y) : "f"(x));
    return y;
}
__device__ __forceinline__ uint32_t smem_u32(const void* p) {
    uint32_t a;
    asm("{ .reg .u64 t; cvta.to.shared.u64 t, %1; cvt.u32.u64 %0, t; }"
        : "=r"(a) : "l"(p));
    return a;
}
__device__ __forceinline__ void mma16(float* d, const uint32_t* a, const uint32_t* b) {
    asm volatile(
        "mma.sync.aligned.m16n8k16.row.col.f32.f16.f16.f32 "
        "{%0,%1,%2,%3}, {%4,%5,%6,%7}, {%8,%9}, {%0,%1,%2,%3};\n"
        : "+f"(d[0]), "+f"(d[1]), "+f"(d[2]), "+f"(d[3])
        : "r"(a[0]), "r"(a[1]), "r"(a[2]), "r"(a[3]), "r"(b[0]), "r"(b[1]));
}
__device__ __forceinline__ void cp16(uint32_t sm, const void* gm) {
    asm volatile("cp.async.cg.shared.global [%0], [%1], 16;" :: "r"(sm), "l"(gm));
}
__device__ __forceinline__ void cp_commit() {
    asm volatile("cp.async.commit_group;" ::: "memory");
}
template<int N> __device__ __forceinline__ void cp_wait() {
    asm volatile("cp.async.wait_group %0;" :: "n"(N) : "memory");
}
__device__ __forceinline__ void ldsm4(uint32_t* r, uint32_t addr) {
    asm volatile("ldmatrix.sync.aligned.m8n8.x4.shared.b16 {%0,%1,%2,%3}, [%4];"
        : "=r"(r[0]), "=r"(r[1]), "=r"(r[2]), "=r"(r[3]) : "r"(addr));
}
__device__ __forceinline__ void ldsm4t(uint32_t* r, uint32_t addr) {
    asm volatile("ldmatrix.sync.aligned.m8n8.x4.trans.shared.b16 {%0,%1,%2,%3}, [%4];"
        : "=r"(r[0]), "=r"(r[1]), "=r"(r[2]), "=r"(r[3]) : "r"(addr));
}

// ---------------------------------------------------------------------------
// fp32 -> fp16 convert (one-time pass)
// ---------------------------------------------------------------------------
__global__ void f2h_kernel(const float4* __restrict__ src, uint2* __restrict__ dst, int n4)
{
    int i = blockIdx.x * blockDim.x + threadIdx.x;
    if (i < n4) {
        float4 v = src[i];
        dst[i] = make_uint2(f2h2(v.x, v.y), f2h2(v.z, v.w));
    }
}

// ---------------------------------------------------------------------------
// FP16 GEMM via cp.async + ldmatrix (unchanged from R9):
// C[M,N] = A[M,K] @ W[N,K]^T + bias[N]; CTA 128x128, 4 warps 64x64, BK=32.
// smem: row-major 128 rows x 64B, off = row*64 + ((c16 ^ ((row>>1)&3))<<4)
// ---------------------------------------------------------------------------
#define G_STAGE_BYTES 16384
#define G_SMEM_BYTES  (3 * G_STAGE_BYTES)   // 49152

template<bool OUT_HALF>
__global__ __launch_bounds__(128, 2) void gemm_ldsm(
    const __half* __restrict__ A,
    const __half* __restrict__ W0, const __half* __restrict__ W1, const __half* __restrict__ W2,
    const float* __restrict__ b0, const float* __restrict__ b1, const float* __restrict__ b2,
    void* __restrict__ C0, void* __restrict__ C1, void* __restrict__ C2)
{
    extern __shared__ char gsm[];
    const int z = blockIdx.z;
    const __half* W    = (z == 0) ? W0 : (z == 1) ? W1 : W2;
    const float*  bias = (z == 0) ? b0 : (z == 1) ? b1 : b2;
    void*         Cv   = (z == 0) ? C0 : (z == 1) ? C1 : C2;

    const int tid  = threadIdx.x;
    const int lane = tid & 31;
    const int warp = tid >> 5;
    const int mw   = (warp >> 1) * 64;
    const int nw   = (warp & 1) * 64;
    const int block_m = blockIdx.y * 128;
    const int block_n = blockIdx.x * 128;
    const uint32_t smb = smem_u32(gsm);

    const int p_row = tid >> 2;
    const int p_c16 = tid & 3;

    float acc[4][8][4];
    #pragma unroll
    for (int mt = 0; mt < 4; mt++)
        #pragma unroll
        for (int nt = 0; nt < 8; nt++)
            #pragma unroll
            for (int r = 0; r < 4; r++) acc[mt][nt][r] = 0.f;

    auto stage_copy = [&](int st, int kt) {
        const uint32_t sA = smb + st * G_STAGE_BYTES;
        const uint32_t sB = sA + 8192;
        #pragma unroll
        for (int i = 0; i < 4; i++) {
            const int row = p_row + i * 32;
            const uint32_t so = row * 64 + ((p_c16 ^ ((row >> 1) & 3)) << 4);
            cp16(sA + so, A + (size_t)(block_m + row) * DMODEL + kt * 32 + p_c16 * 8);
            cp16(sB + so, W + (size_t)(block_n + row) * DMODEL + kt * 32 + p_c16 * 8);
        }
    };

    stage_copy(0, 0); cp_commit();
    stage_copy(1, 1); cp_commit();

    const int NK = DMODEL / 32;
    const int mat  = lane >> 3;
    const int lrow = lane & 7;
    int st = 0;

    for (int kt = 0; kt < NK; ++kt) {
        cp_wait<1>();
        __syncthreads();
        if (kt + 2 < NK) stage_copy((st + 2) % 3, kt + 2);
        cp_commit();

        const uint32_t sA = smb + st * G_STAGE_BYTES;
        const uint32_t sB = sA + 8192;

        #pragma unroll
        for (int ks = 0; ks < 2; ++ks) {
            uint32_t a[4][4];
            #pragma unroll
            for (int mt = 0; mt < 4; mt++) {
                const int row = mw + mt * 16 + (mat & 1) * 8 + lrow;
                const int c16 = ks * 2 + (mat >> 1);
                ldsm4(a[mt], sA + row * 64 + ((c16 ^ ((row >> 1) & 3)) << 4));
            }
            uint32_t bb[4][4];
            #pragma unroll
            for (int np = 0; np < 4; np++) {
                const int row = nw + np * 16 + (mat >> 1) * 8 + lrow;
                const int c16 = ks * 2 + (mat & 1);
                ldsm4(bb[np], sB + row * 64 + ((c16 ^ ((row >> 1) & 3)) << 4));
            }
            #pragma unroll
            for (int mt = 0; mt < 4; mt++)
                #pragma unroll
                for (int np = 0; np < 4; np++) {
                    mma16(acc[mt][np * 2],     a[mt], &bb[np][0]);
                    mma16(acc[mt][np * 2 + 1], a[mt], &bb[np][2]);
                }
        }
        __syncthreads();
        st = (st + 1) % 3;
    }

    const int gid = lane >> 2, tig = lane & 3;
    #pragma unroll
    for (int mt = 0; mt < 4; mt++) {
        const int row = block_m + mw + mt * 16 + gid;
        #pragma unroll
        for (int nt = 0; nt < 8; nt++) {
            const int col = block_n + nw + nt * 8 + tig * 2;
            const float bx = __ldg(bias + col), by = __ldg(bias + col + 1);
            const float v00 = acc[mt][nt][0] + bx, v01 = acc[mt][nt][1] + by;
            const float v10 = acc[mt][nt][2] + bx, v11 = acc[mt][nt][3] + by;
            if (OUT_HALF) {
                __half* C = (__half*)Cv;
                *(uint32_t*)(C + (size_t)row * DMODEL + col)       = f2h2(v00, v01);
                *(uint32_t*)(C + (size_t)(row + 8) * DMODEL + col) = f2h2(v10, v11);
            } else {
                float* C = (float*)Cv;
                *(float2*)(C + (size_t)row * DMODEL + col)       = make_float2(v00, v01);
                *(float2*)(C + (size_t)(row + 8) * DMODEL + col) = make_float2(v10, v11);
            }
        }
    }
}

// ---------------------------------------------------------------------------
// Flash attention, cp.async + ldmatrix, P in registers.
// Block 256 thr = 8 warps; warp owns 16 q rows (128 q / CTA).
// K/V tiles: 128 keys x 64 dh fp16, row-major 128B rows,
//   off(row,c16) = row*128 + ((c16 ^ (row&7))<<4),  2-stage pipeline.
// Q tile staged once. S scaled in fp32; exp2-domain softmax.
// ---------------------------------------------------------------------------
#define AT_TILE_BYTES 16384                      // one 128x128B tile
#define AT_SMEM_BYTES (AT_TILE_BYTES * 5)        // Q + 2 stages x (K,V) = 80KB

__global__ __launch_bounds__(256, 2) void attn_mma(
    const __half* __restrict__ Qp, const __half* __restrict__ Kp,
    const __half* __restrict__ Vp, __half* __restrict__ Ctx)
{
    extern __shared__ char asmm[];
    const uint32_t uQ = smem_u32(asmm);
    const uint32_t uS = uQ + AT_TILE_BYTES;      // stage s: K at uS+s*32768, V +16384

    const int tid  = threadIdx.x;
    const int lane = tid & 31;
    const int warp = tid >> 5;
    const int gid  = lane >> 2;
    const int tig  = lane & 3;
    const int mat  = lane >> 3;
    const int lrow = lane & 7;
    const int q0   = warp * 16;

    const int b     = blockIdx.z;
    const int h     = blockIdx.y;
    const int q_blk = blockIdx.x * 128;

    const float SCL = 0.125f * 1.4426950408889634f;   // 1/sqrt(64) * log2(e)

    const __half* qbase = Qp + (size_t)(b * SEQ + q_blk) * DMODEL + h * DHEAD;
    const __half* kbase = Kp + (size_t)(b * SEQ) * DMODEL + h * DHEAD;
    const __half* vbase = Vp + (size_t)(b * SEQ) * DMODEL + h * DHEAD;

    // producer coords: 256 thr cover 32 rows x 8 c16 per pass, 4 passes
    const int p_row = tid >> 3;      // 0..31
    const int p_c16 = tid & 7;

    auto soff = [&](int row, int c16) -> uint32_t {
        return (uint32_t)(row * 128 + ((c16 ^ (row & 7)) << 4));
    };
    auto stage_kv = [&](int st, int kt) {
        const uint32_t uK = uS + st * (2 * AT_TILE_BYTES);
        const uint32_t uV = uK + AT_TILE_BYTES;
        #pragma unroll
        for (int i = 0; i < 4; i++) {
            const int row = p_row + i * 32;
            const size_t g = (size_t)(kt * 128 + row) * DMODEL + p_c16 * 8;
            const uint32_t so = soff(row, p_c16);
            cp16(uK + so, kbase + g);
            cp16(uV + so, vbase + g);
        }
    };

    // ---- Q copy (group 0), tile 0 (group 1) ----
    #pragma unroll
    for (int i = 0; i < 4; i++) {
        const int row = p_row + i * 32;
        cp16(uQ + soff(row, p_c16), qbase + (size_t)row * DMODEL + p_c16 * 8);
    }
    cp_commit();
    stage_kv(0, 0);
    cp_commit();

    cp_wait<1>();        // Q arrived
    __syncthreads();

    // ---- Q A-fragments ----
    uint32_t aq[4][4];
    #pragma unroll
    for (int ks = 0; ks < 4; ks++) {
        const int row = q0 + (mat & 1) * 8 + lrow;
        const int c16 = ks * 2 + (mat >> 1);
        ldsm4(aq[ks], uQ + soff(row, c16));
    }

    float o[8][4];
    #pragma unroll
    for (int dt = 0; dt < 8; dt++)
        #pragma unroll
        for (int r = 0; r < 4; r++) o[dt][r] = 0.f;
    float m0 = -1e30f, m1 = -1e30f, l0 = 0.f, l1 = 0.f;

    const int NT = SEQ / 128;   // 16
    for (int kt = 0; kt < NT; ++kt) {
        const int buf = kt & 1;
        if (kt + 1 < NT) stage_kv(buf ^ 1, kt + 1);
        cp_commit();
        cp_wait<1>();           // tile kt arrived
        __syncthreads();

        const uint32_t uK = uS + buf * (2 * AT_TILE_BYTES);
        const uint32_t uV = uK + AT_TILE_BYTES;

        #pragma unroll
        for (int hf = 0; hf < 2; ++hf) {
            // ---- S = Q K^T ----
            float s[8][4];
            #pragma unroll
            for (int nt = 0; nt < 8; nt++)
                #pragma unroll
                for (int r = 0; r < 4; r++) s[nt][r] = 0.f;

            #pragma unroll
            for (int ks = 0; ks < 4; ks++) {
                uint32_t kb[4][4];
                #pragma unroll
                for (int np = 0; np < 4; np++) {
                    const int row = hf * 64 + np * 16 + (mat >> 1) * 8 + lrow;
                    const int c16 = ks * 2 + (mat & 1);
                    ldsm4(kb[np], uK + soff(row, c16));
                }
                #pragma unroll
                for (int np = 0; np < 4; np++) {
                    mma16(s[np * 2],     aq[ks], &kb[np][0]);
                    mma16(s[np * 2 + 1], aq[ks], &kb[np][2]);
                }
            }

            // ---- scale + online softmax (exp2 domain) ----
            #pragma unroll
            for (int nt = 0; nt < 8; nt++) {
                s[nt][0] *= SCL; s[nt][1] *= SCL;
                s[nt][2] *= SCL; s[nt][3] *= SCL;
            }
            float mx0 = -1e30f, mx1 = -1e30f;
            #pragma unroll
            for (int nt = 0; nt < 8; nt++) {
                mx0 = fmaxf(mx0, fmaxf(s[nt][0], s[nt][1]));
                mx1 = fmaxf(mx1, fmaxf(s[nt][2], s[nt][3]));
            }
            mx0 = fmaxf(mx0, __shfl_xor_sync(0xffffffffu, mx0, 1));
            mx0 = fmaxf(mx0, __shfl_xor_sync(0xffffffffu, mx0, 2));
            mx1 = fmaxf(mx1, __shfl_xor_sync(0xffffffffu, mx1, 1));
            mx1 = fmaxf(mx1, __shfl_xor_sync(0xffffffffu, mx1, 2));

            const float nm0 = fmaxf(m0, mx0), nm1 = fmaxf(m1, mx1);
            const float c0 = ex2f(m0 - nm0), c1 = ex2f(m1 - nm1);
            m0 = nm0; m1 = nm1;

            float ls0 = 0.f, ls1 = 0.f;
            #pragma unroll
            for (int nt = 0; nt < 8; nt++) {
                s[nt][0] = ex2f(s[nt][0] - m0);
                s[nt][1] = ex2f(s[nt][1] - m0);
                s[nt][2] = ex2f(s[nt][2] - m1);
                s[nt][3] = ex2f(s[nt][3] - m1);
                ls0 += s[nt][0] + s[nt][1];
                ls1 += s[nt][2] + s[nt][3];
            }
            l0 = l0 * c0 + ls0;
            l1 = l1 * c1 + ls1;
            #pragma unroll
            for (int dt = 0; dt < 8; dt++) {
                o[dt][0] *= c0; o[dt][1] *= c0;
                o[dt][2] *= c1; o[dt][3] *= c1;
            }

            // ---- O += P V : P built in registers from S (C-frag == A-frag) ----
            #pragma unroll
            for (int ks = 0; ks < 4; ks++) {
                uint32_t ap[4];
                ap[0] = f2h2(s[2*ks][0],     s[2*ks][1]);
                ap[1] = f2h2(s[2*ks][2],     s[2*ks][3]);
                ap[2] = f2h2(s[2*ks+1][0],   s[2*ks+1][1]);
                ap[3] = f2h2(s[2*ks+1][2],   s[2*ks+1][3]);

                uint32_t vb[4][4];
                #pragma unroll
                for (int np = 0; np < 4; np++) {
                    const int row = hf * 64 + ks * 16 + (mat & 1) * 8 + lrow;
                    const int c16 = np * 2 + (mat >> 1);
                    ldsm4t(vb[np], uV + soff(row, c16));
                }
                #pragma unroll
                for (int np = 0; np < 4; np++) {
                    mma16(o[np * 2],     ap, &vb[np][0]);
                    mma16(o[np * 2 + 1], ap, &vb[np][2]);
                }
            }
        }
        __syncthreads();   // all warps done with buf before it is re-staged
    }

    // ---- finalize (fp16 out) ----
    l0 += __shfl_xor_sync(0xffffffffu, l0, 1);
    l0 += __shfl_xor_sync(0xffffffffu, l0, 2);
    l1 += __shfl_xor_sync(0xffffffffu, l1, 1);
    l1 += __shfl_xor_sync(0xffffffffu, l1, 2);
    const float i0 = 1.f / l0, i1 = 1.f / l1;

    __half* cp0 = Ctx + (size_t)(b * SEQ + q_blk + q0 + gid) * DMODEL + h * DHEAD;
    __half* cp1 = cp0 + (size_t)8 * DMODEL;
    #pragma unroll
    for (int nt = 0; nt < 8; nt++) {
        const int col = nt * 8 + tig * 2;
        *(uint32_t*)(cp0 + col) = f2h2(o[nt][0] * i0, o[nt][1] * i0);
        *(uint32_t*)(cp1 + col) = f2h2(o[nt][2] * i1, o[nt][3] * i1);
    }
}

// ---------------------------------------------------------------------------
extern "C" void kernel_launch(void* const* d_in, const int* in_sizes, int n_in,
                              void* d_out, int out_size)
{
    const float* x  = (const float*)d_in[0];
    const float* Wq = (const float*)d_in[1];
    const float* bq = (const float*)d_in[2];
    const float* Wk = (const float*)d_in[3];
    const float* bk = (const float*)d_in[4];
    const float* Wv = (const float*)d_in[5];
    const float* bv = (const float*)d_in[6];
    const float* Wo = (const float*)d_in[7];
    const float* bo = (const float*)d_in[8];
    float* out = (float*)d_out;

    __half *Xh, *Wqh, *Wkh, *Wvh, *Woh, *Qh, *Kh, *Vh, *Ch;
    cudaGetSymbolAddress((void**)&Xh,  g_Xh);
    cudaGetSymbolAddress((void**)&Wqh, g_Wqh);
    cudaGetSymbolAddress((void**)&Wkh, g_Wkh);
    cudaGetSymbolAddress((void**)&Wvh, g_Wvh);
    cudaGetSymbolAddress((void**)&Woh, g_Woh);
    cudaGetSymbolAddress((void**)&Qh,  g_Qh);
    cudaGetSymbolAddress((void**)&Kh,  g_Kh);
    cudaGetSymbolAddress((void**)&Vh,  g_Vh);
    cudaGetSymbolAddress((void**)&Ch,  g_Ch);

    static bool attr_set = false;
    if (!attr_set) {
        cudaFuncSetAttribute(attn_mma,
                             cudaFuncAttributeMaxDynamicSharedMemorySize,
                             AT_SMEM_BYTES);
        cudaFuncSetAttribute(gemm_ldsm<true>,
                             cudaFuncAttributeMaxDynamicSharedMemorySize,
                             G_SMEM_BYTES);
        cudaFuncSetAttribute(gemm_ldsm<false>,
                             cudaFuncAttributeMaxDynamicSharedMemorySize,
                             G_SMEM_BYTES);
        attr_set = true;
    }

    // ---- 1. fp32 -> fp16 converts ----
    const int xN4 = MTOT * DMODEL / 4;
    const int wN4 = DMODEL * DMODEL / 4;
    f2h_kernel<<<(xN4 + 255) / 256, 256>>>((const float4*)x,  (uint2*)Xh,  xN4);
    f2h_kernel<<<(wN4 + 255) / 256, 256>>>((const float4*)Wq, (uint2*)Wqh, wN4);
    f2h_kernel<<<(wN4 + 255) / 256, 256>>>((const float4*)Wk, (uint2*)Wkh, wN4);
    f2h_kernel<<<(wN4 + 255) / 256, 256>>>((const float4*)Wv, (uint2*)Wvh, wN4);
    f2h_kernel<<<(wN4 + 255) / 256, 256>>>((const float4*)Wo, (uint2*)Woh, wN4);

    // ---- 2. QKV projections (fused, fp16 out) ----
    dim3 gqkv(DMODEL / 128, MTOT / 128, 3);
    gemm_ldsm<true><<<gqkv, 128, G_SMEM_BYTES>>>(
        Xh, Wqh, Wkh, Wvh, bq, bk, bv, Qh, Kh, Vh);

    // ---- 3. attention ----
    dim3 agrid(SEQ / 128, HEADS, BATCH);
    attn_mma<<<agrid, 256, AT_SMEM_BYTES>>>(Qh, Kh, Vh, Ch);

    // ---- 4. output projection (fp32 out) ----
    dim3 gout(DMODEL / 128, MTOT / 128, 1);
    gemm_ldsm<false><<<gout, 128, G_SMEM_BYTES>>>(
        Ch, Woh, Woh, Woh, bo, bo, bo, out, out, out);
}

// round 12
// speedup vs baseline: 11.3677x; 1.0652x over previous
#include <cuda_runtime.h>
#include <cuda_fp16.h>
#include <cstdint>

#define BATCH   2
#define SEQ     2048
#define DMODEL  1024
#define HEADS   16
#define DHEAD   64
#define MTOT    (BATCH * SEQ)   // 4096

// fp16 intermediates (allocation-free rule: __device__ globals)
__device__ __half g_Xh [MTOT * DMODEL];
__device__ __half g_Wqh[DMODEL * DMODEL];
__device__ __half g_Wkh[DMODEL * DMODEL];
__device__ __half g_Wvh[DMODEL * DMODEL];
__device__ __half g_Woh[DMODEL * DMODEL];
__device__ __half g_Qh [MTOT * DMODEL];
__device__ __half g_Kh [MTOT * DMODEL];
__device__ __half g_Vh [MTOT * DMODEL];
__device__ __half g_Ch [MTOT * DMODEL];

// ---------------------------------------------------------------------------
// helpers
// ---------------------------------------------------------------------------
__device__ __forceinline__ uint32_t f2h2(float lo, float hi) {
    __half2 h = __floats2half2_rn(lo, hi);
    return *(uint32_t*)&h;
}
__device__ __forceinline__ float ex2f(float x) {
    float y;
    asm("ex2.approx.ftz.f32 %0, %1;" : "=f"(y) : "f"(x));
    return y;
}
__device__ __forceinline__ uint32_t ex2h2(uint32_t a) {
    uint32_t y;
    asm("ex2.approx.f16x2 %0, %1;" : "=r"(y) : "r"(a));
    return y;
}
__device__ __forceinline__ uint32_t smem_u32(const void* p) {
    uint32_t a;
    asm("{ .reg .u64 t; cvta.to.shared.u64 t, %1; cvt.u32.u64 %0, t; }"
        : "=r"(a) : "l"(p));
    return a;
}
__device__ __forceinline__ void mma16(float* d, const uint32_t* a, const uint32_t* b) {
    asm volatile(
        "mma.sync.aligned.m16n8k16.row.col.f32.f16.f16.f32 "
        "{%0,%1,%2,%3}, {%4,%5,%6,%7}, {%8,%9}, {%0,%1,%2,%3};\n"
        : "+f"(d[0]), "+f"(d[1]), "+f"(d[2]), "+f"(d[3])
        : "r"(a[0]), "r"(a[1]), "r"(a[2]), "r"(a[3]), "r"(b[0]), "r"(b[1]));
}
__device__ __forceinline__ void cp16(uint32_t sm, const void* gm) {
    asm volatile("cp.async.cg.shared.global [%0], [%1], 16;" :: "r"(sm), "l"(gm));
}
__device__ __forceinline__ void cp_commit() {
    asm volatile("cp.async.commit_group;" ::: "memory");
}
template<int N> __device__ __forceinline__ void cp_wait() {
    asm volatile("cp.async.wait_group %0;" :: "n"(N) : "memory");
}
__device__ __forceinline__ void ldsm4(uint32_t* r, uint32_t addr) {
    asm volatile("ldmatrix.sync.aligned.m8n8.x4.shared.b16 {%0,%1,%2,%3}, [%4];"
        : "=r"(r[0]), "=r"(r[1]), "=r"(r[2]), "=r"(r[3]) : "r"(addr));
}
__device__ __forceinline__ void ldsm4t(uint32_t* r, uint32_t addr) {
    asm volatile("ldmatrix.sync.aligned.m8n8.x4.trans.shared.b16 {%0,%1,%2,%3}, [%4];"
        : "=r"(r[0]), "=r"(r[1]), "=r"(r[2]), "=r"(r[3]) : "r"(addr));
}

// ---------------------------------------------------------------------------
// fused fp32 -> fp16 convert: one launch, grid.y selects tensor
// ---------------------------------------------------------------------------
__global__ void f2h_all(
    const float4* __restrict__ x,  const float4* __restrict__ wq,
    const float4* __restrict__ wk, const float4* __restrict__ wv,
    const float4* __restrict__ wo,
    uint2* __restrict__ xh,  uint2* __restrict__ wqh, uint2* __restrict__ wkh,
    uint2* __restrict__ wvh, uint2* __restrict__ woh)
{
    const float4* src;
    uint2* dst;
    int n4;
    switch (blockIdx.y) {
        case 0:  src = x;  dst = xh;  n4 = MTOT * DMODEL / 4;   break;
        case 1:  src = wq; dst = wqh; n4 = DMODEL * DMODEL / 4; break;
        case 2:  src = wk; dst = wkh; n4 = DMODEL * DMODEL / 4; break;
        case 3:  src = wv; dst = wvh; n4 = DMODEL * DMODEL / 4; break;
        default: src = wo; dst = woh; n4 = DMODEL * DMODEL / 4; break;
    }
    for (int i = blockIdx.x * blockDim.x + threadIdx.x; i < n4;
         i += gridDim.x * blockDim.x) {
        float4 v = src[i];
        dst[i] = make_uint2(f2h2(v.x, v.y), f2h2(v.z, v.w));
    }
}

// ---------------------------------------------------------------------------
// FP16 GEMM via cp.async + ldmatrix (unchanged from R10):
// C[M,N] = A[M,K] @ W[N,K]^T + bias[N]; CTA 128x128, 4 warps 64x64, BK=32.
// ---------------------------------------------------------------------------
#define G_STAGE_BYTES 16384
#define G_SMEM_BYTES  (3 * G_STAGE_BYTES)   // 49152

template<bool OUT_HALF>
__global__ __launch_bounds__(128, 2) void gemm_ldsm(
    const __half* __restrict__ A,
    const __half* __restrict__ W0, const __half* __restrict__ W1, const __half* __restrict__ W2,
    const float* __restrict__ b0, const float* __restrict__ b1, const float* __restrict__ b2,
    void* __restrict__ C0, void* __restrict__ C1, void* __restrict__ C2)
{
    extern __shared__ char gsm[];
    const int z = blockIdx.z;
    const __half* W    = (z == 0) ? W0 : (z == 1) ? W1 : W2;
    const float*  bias = (z == 0) ? b0 : (z == 1) ? b1 : b2;
    void*         Cv   = (z == 0) ? C0 : (z == 1) ? C1 : C2;

    const int tid  = threadIdx.x;
    const int lane = tid & 31;
    const int warp = tid >> 5;
    const int mw   = (warp >> 1) * 64;
    const int nw   = (warp & 1) * 64;
    const int block_m = blockIdx.y * 128;
    const int block_n = blockIdx.x * 128;
    const uint32_t smb = smem_u32(gsm);

    const int p_row = tid >> 2;
    const int p_c16 = tid & 3;

    float acc[4][8][4];
    #pragma unroll
    for (int mt = 0; mt < 4; mt++)
        #pragma unroll
        for (int nt = 0; nt < 8; nt++)
            #pragma unroll
            for (int r = 0; r < 4; r++) acc[mt][nt][r] = 0.f;

    auto stage_copy = [&](int st, int kt) {
        const uint32_t sA = smb + st * G_STAGE_BYTES;
        const uint32_t sB = sA + 8192;
        #pragma unroll
        for (int i = 0; i < 4; i++) {
            const int row = p_row + i * 32;
            const uint32_t so = row * 64 + ((p_c16 ^ ((row >> 1) & 3)) << 4);
            cp16(sA + so, A + (size_t)(block_m + row) * DMODEL + kt * 32 + p_c16 * 8);
            cp16(sB + so, W + (size_t)(block_n + row) * DMODEL + kt * 32 + p_c16 * 8);
        }
    };

    stage_copy(0, 0); cp_commit();
    stage_copy(1, 1); cp_commit();

    const int NK = DMODEL / 32;
    const int mat  = lane >> 3;
    const int lrow = lane & 7;
    int st = 0;

    for (int kt = 0; kt < NK; ++kt) {
        cp_wait<1>();
        __syncthreads();
        if (kt + 2 < NK) stage_copy((st + 2) % 3, kt + 2);
        cp_commit();

        const uint32_t sA = smb + st * G_STAGE_BYTES;
        const uint32_t sB = sA + 8192;

        #pragma unroll
        for (int ks = 0; ks < 2; ++ks) {
            uint32_t a[4][4];
            #pragma unroll
            for (int mt = 0; mt < 4; mt++) {
                const int row = mw + mt * 16 + (mat & 1) * 8 + lrow;
                const int c16 = ks * 2 + (mat >> 1);
                ldsm4(a[mt], sA + row * 64 + ((c16 ^ ((row >> 1) & 3)) << 4));
            }
            uint32_t bb[4][4];
            #pragma unroll
            for (int np = 0; np < 4; np++) {
                const int row = nw + np * 16 + (mat >> 1) * 8 + lrow;
                const int c16 = ks * 2 + (mat & 1);
                ldsm4(bb[np], sB + row * 64 + ((c16 ^ ((row >> 1) & 3)) << 4));
            }
            #pragma unroll
            for (int mt = 0; mt < 4; mt++)
                #pragma unroll
                for (int np = 0; np < 4; np++) {
                    mma16(acc[mt][np * 2],     a[mt], &bb[np][0]);
                    mma16(acc[mt][np * 2 + 1], a[mt], &bb[np][2]);
                }
        }
        __syncthreads();
        st = (st + 1) % 3;
    }

    const int gid = lane >> 2, tig = lane & 3;
    #pragma unroll
    for (int mt = 0; mt < 4; mt++) {
        const int row = block_m + mw + mt * 16 + gid;
        #pragma unroll
        for (int nt = 0; nt < 8; nt++) {
            const int col = block_n + nw + nt * 8 + tig * 2;
            const float bx = __ldg(bias + col), by = __ldg(bias + col + 1);
            const float v00 = acc[mt][nt][0] + bx, v01 = acc[mt][nt][1] + by;
            const float v10 = acc[mt][nt][2] + bx, v11 = acc[mt][nt][3] + by;
            if (OUT_HALF) {
                __half* C = (__half*)Cv;
                *(uint32_t*)(C + (size_t)row * DMODEL + col)       = f2h2(v00, v01);
                *(uint32_t*)(C + (size_t)(row + 8) * DMODEL + col) = f2h2(v10, v11);
            } else {
                float* C = (float*)Cv;
                *(float2*)(C + (size_t)row * DMODEL + col)       = make_float2(v00, v01);
                *(float2*)(C + (size_t)(row + 8) * DMODEL + col) = make_float2(v10, v11);
            }
        }
    }
}

// ---------------------------------------------------------------------------
// Flash attention, cp.async + ldmatrix, P in registers.
// f16x2 ex2 softmax; row-sums l via ones-MMA (no FADD chain, no final shfl).
// Block 256 thr = 8 warps; warp owns 16 q rows (128 q / CTA).
// ---------------------------------------------------------------------------
#define AT_TILE_BYTES 16384
#define AT_SMEM_BYTES (AT_TILE_BYTES * 5)        // Q + 2 stages x (K,V) = 80KB

__global__ __launch_bounds__(256, 2) void attn_mma(
    const __half* __restrict__ Qp, const __half* __restrict__ Kp,
    const __half* __restrict__ Vp, __half* __restrict__ Ctx)
{
    extern __shared__ char asmm[];
    const uint32_t uQ = smem_u32(asmm);
    const uint32_t uS = uQ + AT_TILE_BYTES;

    const int tid  = threadIdx.x;
    const int lane = tid & 31;
    const int warp = tid >> 5;
    const int gid  = lane >> 2;
    const int tig  = lane & 3;
    const int mat  = lane >> 3;
    const int lrow = lane & 7;
    const int q0   = warp * 16;

    const int b     = blockIdx.z;
    const int h     = blockIdx.y;
    const int q_blk = blockIdx.x * 128;

    const float SCL = 0.125f * 1.4426950408889634f;   // 1/sqrt(64) * log2(e)
    const uint32_t ONES2[2] = { 0x3C003C00u, 0x3C003C00u };  // half2(1,1) x2

    const __half* qbase = Qp + (size_t)(b * SEQ + q_blk) * DMODEL + h * DHEAD;
    const __half* kbase = Kp + (size_t)(b * SEQ) * DMODEL + h * DHEAD;
    const __half* vbase = Vp + (size_t)(b * SEQ) * DMODEL + h * DHEAD;

    const int p_row = tid >> 3;
    const int p_c16 = tid & 7;

    auto soff = [&](int row, int c16) -> uint32_t {
        return (uint32_t)(row * 128 + ((c16 ^ (row & 7)) << 4));
    };
    auto stage_kv = [&](int st, int kt) {
        const uint32_t uK = uS + st * (2 * AT_TILE_BYTES);
        const uint32_t uV = uK + AT_TILE_BYTES;
        #pragma unroll
        for (int i = 0; i < 4; i++) {
            const int row = p_row + i * 32;
            const size_t g = (size_t)(kt * 128 + row) * DMODEL + p_c16 * 8;
            const uint32_t so = soff(row, p_c16);
            cp16(uK + so, kbase + g);
            cp16(uV + so, vbase + g);
        }
    };

    // ---- Q copy (group 0), tile 0 (group 1) ----
    #pragma unroll
    for (int i = 0; i < 4; i++) {
        const int row = p_row + i * 32;
        cp16(uQ + soff(row, p_c16), qbase + (size_t)row * DMODEL + p_c16 * 8);
    }
    cp_commit();
    stage_kv(0, 0);
    cp_commit();

    cp_wait<1>();
    __syncthreads();

    uint32_t aq[4][4];
    #pragma unroll
    for (int ks = 0; ks < 4; ks++) {
        const int row = q0 + (mat & 1) * 8 + lrow;
        const int c16 = ks * 2 + (mat >> 1);
        ldsm4(aq[ks], uQ + soff(row, c16));
    }

    float o[8][4];
    #pragma unroll
    for (int dt = 0; dt < 8; dt++)
        #pragma unroll
        for (int r = 0; r < 4; r++) o[dt][r] = 0.f;
    float lacc[4] = { 0.f, 0.f, 0.f, 0.f };   // l via ones-MMA C-frag
    float m0 = -1e30f, m1 = -1e30f;

    const int NT = SEQ / 128;   // 16
    for (int kt = 0; kt < NT; ++kt) {
        const int buf = kt & 1;
        if (kt + 1 < NT) stage_kv(buf ^ 1, kt + 1);
        cp_commit();
        cp_wait<1>();
        __syncthreads();

        const uint32_t uK = uS + buf * (2 * AT_TILE_BYTES);
        const uint32_t uV = uK + AT_TILE_BYTES;

        #pragma unroll
        for (int hf = 0; hf < 2; ++hf) {
            // ---- S = Q K^T (raw scores) ----
            float s[8][4];
            #pragma unroll
            for (int nt = 0; nt < 8; nt++)
                #pragma unroll
                for (int r = 0; r < 4; r++) s[nt][r] = 0.f;

            #pragma unroll
            for (int ks = 0; ks < 4; ks++) {
                uint32_t kb[4][4];
                #pragma unroll
                for (int np = 0; np < 4; np++) {
                    const int row = hf * 64 + np * 16 + (mat >> 1) * 8 + lrow;
                    const int c16 = ks * 2 + (mat & 1);
                    ldsm4(kb[np], uK + soff(row, c16));
                }
                #pragma unroll
                for (int np = 0; np < 4; np++) {
                    mma16(s[np * 2],     aq[ks], &kb[np][0]);
                    mma16(s[np * 2 + 1], aq[ks], &kb[np][2]);
                }
            }

            // ---- online softmax: max on raw scores, scale folded into exp arg ----
            float mx0 = -1e30f, mx1 = -1e30f;
            #pragma unroll
            for (int nt = 0; nt < 8; nt++) {
                mx0 = fmaxf(mx0, fmaxf(s[nt][0], s[nt][1]));
                mx1 = fmaxf(mx1, fmaxf(s[nt][2], s[nt][3]));
            }
            mx0 = fmaxf(mx0, __shfl_xor_sync(0xffffffffu, mx0, 1));
            mx0 = fmaxf(mx0, __shfl_xor_sync(0xffffffffu, mx0, 2));
            mx1 = fmaxf(mx1, __shfl_xor_sync(0xffffffffu, mx1, 1));
            mx1 = fmaxf(mx1, __shfl_xor_sync(0xffffffffu, mx1, 2));

            const float nm0 = fmaxf(m0, mx0), nm1 = fmaxf(m1, mx1);
            const float c0 = ex2f((m0 - nm0) * SCL), c1 = ex2f((m1 - nm1) * SCL);
            m0 = nm0; m1 = nm1;
            const float b0s = nm0 * SCL, b1s = nm1 * SCL;

            // ---- P = 2^(s*SCL - m*SCL) via f16x2 ex2 -> PV A-frags directly ----
            uint32_t ph[8][2];
            #pragma unroll
            for (int nt = 0; nt < 8; nt++) {
                const float a0 = fmaf(s[nt][0], SCL, -b0s);
                const float a1 = fmaf(s[nt][1], SCL, -b0s);
                const float a2 = fmaf(s[nt][2], SCL, -b1s);
                const float a3 = fmaf(s[nt][3], SCL, -b1s);
                ph[nt][0] = ex2h2(f2h2(a0, a1));
                ph[nt][1] = ex2h2(f2h2(a2, a3));
            }

            // ---- rescale running state ----
            lacc[0] *= c0; lacc[1] *= c0; lacc[2] *= c1; lacc[3] *= c1;
            #pragma unroll
            for (int dt = 0; dt < 8; dt++) {
                o[dt][0] *= c0; o[dt][1] *= c0;
                o[dt][2] *= c1; o[dt][3] *= c1;
            }

            // ---- O += P V ; l += P @ 1 ----
            #pragma unroll
            for (int ks = 0; ks < 4; ks++) {
                uint32_t ap[4] = { ph[2*ks][0], ph[2*ks][1],
                                   ph[2*ks+1][0], ph[2*ks+1][1] };
                mma16(lacc, ap, ONES2);

                uint32_t vb[4][4];
                #pragma unroll
                for (int np = 0; np < 4; np++) {
                    const int row = hf * 64 + ks * 16 + (mat & 1) * 8 + lrow;
                    const int c16 = np * 2 + (mat >> 1);
                    ldsm4t(vb[np], uV + soff(row, c16));
                }
                #pragma unroll
                for (int np = 0; np < 4; np++) {
                    mma16(o[np * 2],     ap, &vb[np][0]);
                    mma16(o[np * 2 + 1], ap, &vb[np][2]);
                }
            }
        }
        __syncthreads();
    }

    // ---- finalize: lacc already fully reduced over keys by the MMA ----
    const float i0 = 1.f / lacc[0], i1 = 1.f / lacc[2];

    __half* cp0 = Ctx + (size_t)(b * SEQ + q_blk + q0 + gid) * DMODEL + h * DHEAD;
    __half* cp1 = cp0 + (size_t)8 * DMODEL;
    #pragma unroll
    for (int nt = 0; nt < 8; nt++) {
        const int col = nt * 8 + tig * 2;
        *(uint32_t*)(cp0 + col) = f2h2(o[nt][0] * i0, o[nt][1] * i0);
        *(uint32_t*)(cp1 + col) = f2h2(o[nt][2] * i1, o[nt][3] * i1);
    }
}

// ---------------------------------------------------------------------------
extern "C" void kernel_launch(void* const* d_in, const int* in_sizes, int n_in,
                              void* d_out, int out_size)
{
    const float* x  = (const float*)d_in[0];
    const float* Wq = (const float*)d_in[1];
    const float* bq = (const float*)d_in[2];
    const float* Wk = (const float*)d_in[3];
    const float* bk = (const float*)d_in[4];
    const float* Wv = (const float*)d_in[5];
    const float* bv = (const float*)d_in[6];
    const float* Wo = (const float*)d_in[7];
    const float* bo = (const float*)d_in[8];
    float* out = (float*)d_out;

    __half *Xh, *Wqh, *Wkh, *Wvh, *Woh, *Qh, *Kh, *Vh, *Ch;
    cudaGetSymbolAddress((void**)&Xh,  g_Xh);
    cudaGetSymbolAddress((void**)&Wqh, g_Wqh);
    cudaGetSymbolAddress((void**)&Wkh, g_Wkh);
    cudaGetSymbolAddress((void**)&Wvh, g_Wvh);
    cudaGetSymbolAddress((void**)&Woh, g_Woh);
    cudaGetSymbolAddress((void**)&Qh,  g_Qh);
    cudaGetSymbolAddress((void**)&Kh,  g_Kh);
    cudaGetSymbolAddress((void**)&Vh,  g_Vh);
    cudaGetSymbolAddress((void**)&Ch,  g_Ch);

    static bool attr_set = false;
    if (!attr_set) {
        cudaFuncSetAttribute(attn_mma,
                             cudaFuncAttributeMaxDynamicSharedMemorySize,
                             AT_SMEM_BYTES);
        cudaFuncSetAttribute(gemm_ldsm<true>,
                             cudaFuncAttributeMaxDynamicSharedMemorySize,
                             G_SMEM_BYTES);
        cudaFuncSetAttribute(gemm_ldsm<false>,
                             cudaFuncAttributeMaxDynamicSharedMemorySize,
                             G_SMEM_BYTES);
        attr_set = true;
    }

    // ---- 1. fp32 -> fp16 converts (single fused launch) ----
    dim3 cgrid(512, 5);
    f2h_all<<<cgrid, 256>>>((const float4*)x, (const float4*)Wq,
                            (const float4*)Wk, (const float4*)Wv,
                            (const float4*)Wo,
                            (uint2*)Xh, (uint2*)Wqh, (uint2*)Wkh,
                            (uint2*)Wvh, (uint2*)Woh);

    // ---- 2. QKV projections (fused, fp16 out) ----
    dim3 gqkv(DMODEL / 128, MTOT / 128, 3);
    gemm_ldsm<true><<<gqkv, 128, G_SMEM_BYTES>>>(
        Xh, Wqh, Wkh, Wvh, bq, bk, bv, Qh, Kh, Vh);

    // ---- 3. attention ----
    dim3 agrid(SEQ / 128, HEADS, BATCH);
    attn_mma<<<agrid, 256, AT_SMEM_BYTES>>>(Qh, Kh, Vh, Ch);

    // ---- 4. output projection (fp32 out) ----
    dim3 gout(DMODEL / 128, MTOT / 128, 1);
    gemm_ldsm<false><<<gout, 128, G_SMEM_BYTES>>>(
        Ch, Woh, Woh, Woh, bo, bo, bo, out, out, out);
}